// round 1
// baseline (speedup 1.0000x reference)
#include <cuda_runtime.h>
#include <math.h>

// ---------------- problem constants ----------------
#define BB   2
#define SS   2048
#define DIM_ 2048
#define HH   16
#define DH_  128
#define LAT_ 512
#define DR_  64
#define NQ_  (HH * (DH_ + DR_))   // 3072
#define NKV_ (HH * 2 * DH_)       // 4096
#define NO_  (HH * DH_)           // 2048
#define ROWS (BB * SS)            // 4096

// ---------------- scratch (device globals; no allocation allowed) ----------
__device__ float g_q  [ROWS * (size_t)NQ_];   // 50.3 MB
__device__ float g_ckv[ROWS * (size_t)LAT_];  //  8.4 MB
__device__ float g_kv [ROWS * (size_t)NKV_];  // 67.1 MB
__device__ float g_kr [ROWS * (size_t)DR_];   //  1.0 MB
__device__ float g_att[ROWS * (size_t)NO_];   // 33.6 MB

// ---------------- generic fp32 SGEMM: C = alpha * A[M,K] @ B[K,N] ----------
// 128x128 tile, K-step 8, 256 threads, 8x8 microtile.
__global__ __launch_bounds__(256) void sgemm_k(
    const float* __restrict__ A, const float* __restrict__ Bm,
    float* __restrict__ C, int M, int N, int K, float alpha)
{
    __shared__ float As[8][132];   // stored transposed: As[k][m]
    __shared__ float Bs[8][132];

    const int t  = threadIdx.x;
    const int ty = t >> 4, tx = t & 15;
    const int m0 = blockIdx.y * 128, n0 = blockIdx.x * 128;

    const int ar = t >> 1,  ac = (t & 1)  * 4;   // A loader: 128 rows x 8 cols
    const int br = t >> 5,  bc = (t & 31) * 4;   // B loader: 8 rows x 128 cols

    float acc[8][8];
#pragma unroll
    for (int i = 0; i < 8; i++)
#pragma unroll
        for (int j = 0; j < 8; j++) acc[i][j] = 0.f;

    for (int k0 = 0; k0 < K; k0 += 8) {
        float4 av = *(const float4*)&A[(size_t)(m0 + ar) * K + k0 + ac];
        As[ac + 0][ar] = av.x; As[ac + 1][ar] = av.y;
        As[ac + 2][ar] = av.z; As[ac + 3][ar] = av.w;

        float4 bv = make_float4(0.f, 0.f, 0.f, 0.f);
        if (n0 + bc < N)
            bv = *(const float4*)&Bm[(size_t)(k0 + br) * N + n0 + bc];
        *(float4*)&Bs[br][bc] = bv;
        __syncthreads();

#pragma unroll
        for (int k = 0; k < 8; k++) {
            float a[8], b[8];
            *(float4*)(a)     = *(float4*)&As[k][ty * 8];
            *(float4*)(a + 4) = *(float4*)&As[k][ty * 8 + 4];
            *(float4*)(b)     = *(float4*)&Bs[k][tx * 8];
            *(float4*)(b + 4) = *(float4*)&Bs[k][tx * 8 + 4];
#pragma unroll
            for (int i = 0; i < 8; i++)
#pragma unroll
                for (int j = 0; j < 8; j++) acc[i][j] += a[i] * b[j];
        }
        __syncthreads();
    }

#pragma unroll
    for (int i = 0; i < 8; i++) {
        const int row = m0 + ty * 8 + i;
#pragma unroll
        for (int j = 0; j < 8; j += 4) {
            const int col = n0 + tx * 8 + j;
            if (col < N) {
                float4 v;
                v.x = alpha * acc[i][j + 0];
                v.y = alpha * acc[i][j + 1];
                v.z = alpha * acc[i][j + 2];
                v.w = alpha * acc[i][j + 3];
                *(float4*)&C[(size_t)row * N + col] = v;
            }
        }
    }
}

// ---------------- RoPE ----------------
// q layout: [ROWS, H*(DH+DR)]; rope block = cols [h*192+128, h*192+192)
__global__ void rope_q_k(float* __restrict__ q)
{
    int idx = blockIdx.x * blockDim.x + threadIdx.x;   // ROWS*H*32
    if (idx >= ROWS * HH * 32) return;
    int i   = idx & 31;
    int h   = (idx >> 5) & (HH - 1);
    int row = idx >> 9;
    int pos = row & (SS - 1);
    float inv = powf(10000.0f, -(float)i / 32.0f);
    float ang = (float)pos * inv;
    float s, c; sincosf(ang, &s, &c);
    float* p = q + (size_t)row * NQ_ + h * (DH_ + DR_) + DH_;
    float x1 = p[i], x2 = p[i + 32];
    p[i]      = x1 * c - x2 * s;
    p[i + 32] = x2 * c + x1 * s;
}

__global__ void rope_kr_k(float* __restrict__ kr)
{
    int idx = blockIdx.x * blockDim.x + threadIdx.x;   // ROWS*32
    if (idx >= ROWS * 32) return;
    int i   = idx & 31;
    int row = idx >> 5;
    int pos = row & (SS - 1);
    float inv = powf(10000.0f, -(float)i / 32.0f);
    float ang = (float)pos * inv;
    float s, c; sincosf(ang, &s, &c);
    float* p = kr + (size_t)row * DR_;
    float x1 = p[i], x2 = p[i + 32];
    p[i]      = x1 * c - x2 * s;
    p[i + 32] = x2 * c + x1 * s;
}

// ---------------- flash attention (fp32, causal, online softmax) ----------
// grid (S/128, H, B), 256 threads.
// q pre-scaled by 1/sqrt(DH+DR). kr already roped.
#define BQ_  128
#define BK_  64
#define QSTR 196
#define KSTR 196
#define VSTR 132
#define PSTR 68
#define SMEM_ATTN ((BQ_*QSTR + BK_*KSTR + BK_*VSTR + BQ_*PSTR + 3*BQ_) * 4)

__global__ __launch_bounds__(256) void attn_k(
    const float* __restrict__ q, const float* __restrict__ kv,
    const float* __restrict__ kr, float* __restrict__ outb)
{
    extern __shared__ float sm[];
    float* sQ  = sm;
    float* sK  = sQ  + BQ_ * QSTR;
    float* sV  = sK  + BK_ * KSTR;
    float* sP  = sV  + BK_ * VSTR;
    float* sMx = sP  + BQ_ * PSTR;
    float* sL  = sMx + BQ_;
    float* sA  = sL  + BQ_;

    const int t  = threadIdx.x;
    const int qt = blockIdx.x, h = blockIdx.y, b = blockIdx.z;
    const int q0 = qt * BQ_;
    const int rowg0 = b * SS + q0;

    // load Q tile: 128 rows x 192 floats
    for (int idx = t; idx < BQ_ * 48; idx += 256) {
        int r = idx / 48, c4 = (idx % 48) * 4;
        *(float4*)&sQ[r * QSTR + c4] =
            *(const float4*)&q[(size_t)(rowg0 + r) * NQ_ + h * (DH_ + DR_) + c4];
    }
    if (t < BQ_) { sMx[t] = -1e30f; sL[t] = 0.f; }

    const int rg = t >> 5;            // PV row group (16 rows)
    const int c0 = (t & 31) * 4;      // PV col base
    const int ty = t >> 4, tx = t & 15;

    float O[16][4];
#pragma unroll
    for (int i = 0; i < 16; i++)
#pragma unroll
        for (int j = 0; j < 4; j++) O[i][j] = 0.f;

    const int nkt = 2 * qt + 2;
    for (int kt = 0; kt < nkt; kt++) {
        const int k0 = kt * BK_;
        __syncthreads();
        // load K (nope||rope) and V tiles
        for (int idx = t; idx < BK_ * 32; idx += 256) {
            int r = idx / 32, c4 = (idx % 32) * 4;
            const float* base = &kv[(size_t)(b * SS + k0 + r) * NKV_ + h * 2 * DH_];
            *(float4*)&sK[r * KSTR + c4] = *(const float4*)(base + c4);
            *(float4*)&sV[r * VSTR + c4] = *(const float4*)(base + DH_ + c4);
        }
        for (int idx = t; idx < BK_ * 16; idx += 256) {
            int r = idx / 16, c4 = (idx % 16) * 4;
            *(float4*)&sK[r * KSTR + DH_ + c4] =
                *(const float4*)&kr[(size_t)(b * SS + k0 + r) * DR_ + c4];
        }
        __syncthreads();

        // scores: rows ty*8+i, cols tx+16j (phase-conflict-free LDS.128)
        float s[8][4];
#pragma unroll
        for (int i = 0; i < 8; i++)
#pragma unroll
            for (int j = 0; j < 4; j++) s[i][j] = 0.f;

#pragma unroll 2
        for (int k = 0; k < DH_ + DR_; k += 4) {
            float4 a[8], bb[4];
#pragma unroll
            for (int i = 0; i < 8; i++)
                a[i] = *(float4*)&sQ[(ty * 8 + i) * QSTR + k];
#pragma unroll
            for (int j = 0; j < 4; j++)
                bb[j] = *(float4*)&sK[(tx + 16 * j) * KSTR + k];
#pragma unroll
            for (int i = 0; i < 8; i++)
#pragma unroll
                for (int j = 0; j < 4; j++) {
                    s[i][j] += a[i].x * bb[j].x;
                    s[i][j] += a[i].y * bb[j].y;
                    s[i][j] += a[i].z * bb[j].z;
                    s[i][j] += a[i].w * bb[j].w;
                }
        }

        // mask + online softmax update
#pragma unroll
        for (int i = 0; i < 8; i++) {
            const int lrow = ty * 8 + i;
            const int qrow = q0 + lrow;
            float tm = -1e30f;
#pragma unroll
            for (int j = 0; j < 4; j++) {
                const int kc = k0 + tx + 16 * j;
                if (kc > qrow) s[i][j] = -1e30f;
                tm = fmaxf(tm, s[i][j]);
            }
#pragma unroll
            for (int off = 8; off; off >>= 1)
                tm = fmaxf(tm, __shfl_xor_sync(0xffffffffu, tm, off));
            const float mo = sMx[lrow];
            const float mn = fmaxf(mo, tm);
            float tl = 0.f;
#pragma unroll
            for (int j = 0; j < 4; j++) {
                float p = __expf(s[i][j] - mn);
                s[i][j] = p;
                tl += p;
            }
#pragma unroll
            for (int off = 8; off; off >>= 1)
                tl += __shfl_xor_sync(0xffffffffu, tl, off);
            __syncwarp();
            if (tx == 0) {
                const float al = __expf(mo - mn);
                sA[lrow]  = al;
                sMx[lrow] = mn;
                sL[lrow]  = sL[lrow] * al + tl;
            }
            __syncwarp();
#pragma unroll
            for (int j = 0; j < 4; j++)
                sP[lrow * PSTR + tx + 16 * j] = s[i][j];
        }
        __syncthreads();

        // O = O*alpha + P@V
#pragma unroll
        for (int i = 0; i < 16; i++) {
            const float al = sA[rg * 16 + i];
            O[i][0] *= al; O[i][1] *= al; O[i][2] *= al; O[i][3] *= al;
        }
#pragma unroll 2
        for (int k = 0; k < BK_; k++) {
            const float4 v4 = *(float4*)&sV[k * VSTR + c0];
#pragma unroll
            for (int i = 0; i < 16; i++) {
                const float p = sP[(rg * 16 + i) * PSTR + k];
                O[i][0] += p * v4.x; O[i][1] += p * v4.y;
                O[i][2] += p * v4.z; O[i][3] += p * v4.w;
            }
        }
    }

    // epilogue: divide by l, write [ROWS, H*DH]
#pragma unroll
    for (int i = 0; i < 16; i++) {
        const int lrow = rg * 16 + i;
        const float inv = 1.0f / sL[lrow];
        float4 o;
        o.x = O[i][0] * inv; o.y = O[i][1] * inv;
        o.z = O[i][2] * inv; o.w = O[i][3] * inv;
        *(float4*)&outb[(size_t)(rowg0 + lrow) * NO_ + h * DH_ + c0] = o;
    }
}

// ---------------- launch ----------------
extern "C" void kernel_launch(void* const* d_in, const int* in_sizes, int n_in,
                              void* d_out, int out_size)
{
    const float* x    = (const float*)d_in[0];
    const float* Wq   = (const float*)d_in[1];
    const float* Wdkv = (const float*)d_in[2];
    const float* Wkr  = (const float*)d_in[3];
    const float* Wukv = (const float*)d_in[4];
    const float* Wo   = (const float*)d_in[5];
    float* out = (float*)d_out;

    float* q;   cudaGetSymbolAddress((void**)&q,   g_q);
    float* ckv; cudaGetSymbolAddress((void**)&ckv, g_ckv);
    float* kvb; cudaGetSymbolAddress((void**)&kvb, g_kv);
    float* kr;  cudaGetSymbolAddress((void**)&kr,  g_kr);
    float* att; cudaGetSymbolAddress((void**)&att, g_att);

    const float scale = 1.0f / sqrtf((float)(DH_ + DR_));

    dim3 blk(256);
    // q = scale * x @ Wq   [4096,2048]x[2048,3072]
    sgemm_k<<<dim3(NQ_ / 128, ROWS / 128), blk>>>(x, Wq, q, ROWS, NQ_, DIM_, scale);
    // ckv = x @ Wdkv       [4096,2048]x[2048,512]
    sgemm_k<<<dim3(LAT_ / 128, ROWS / 128), blk>>>(x, Wdkv, ckv, ROWS, LAT_, DIM_, 1.0f);
    // kr = x @ Wkr         [4096,2048]x[2048,64]
    sgemm_k<<<dim3(1, ROWS / 128), blk>>>(x, Wkr, kr, ROWS, DR_, DIM_, 1.0f);
    // kv = ckv @ Wukv      [4096,512]x[512,4096]
    sgemm_k<<<dim3(NKV_ / 128, ROWS / 128), blk>>>(ckv, Wukv, kvb, ROWS, NKV_, LAT_, 1.0f);

    rope_q_k <<<(ROWS * HH * 32 + 255) / 256, blk>>>(q);
    rope_kr_k<<<(ROWS * 32 + 255) / 256, blk>>>(kr);

    cudaFuncSetAttribute(attn_k, cudaFuncAttributeMaxDynamicSharedMemorySize, SMEM_ATTN);
    attn_k<<<dim3(SS / BQ_, HH, BB), blk, SMEM_ATTN>>>(q, kvb, kr, att);

    // out = att @ Wo       [4096,2048]x[2048,2048]
    sgemm_k<<<dim3(DIM_ / 128, ROWS / 128), blk>>>(att, Wo, out, ROWS, DIM_, NO_, 1.0f);
}

// round 3
// speedup vs baseline: 1.6668x; 1.6668x over previous
#include <cuda_runtime.h>
#include <cuda_bf16.h>
#include <math.h>
#include <stdint.h>

// ---------------- problem constants ----------------
#define BB   2
#define SS   2048
#define DIM_ 2048
#define HH   16
#define DH_  128
#define LAT_ 512
#define DR_  64
#define NQ_  (HH * (DH_ + DR_))   // 3072
#define NKV_ (HH * 2 * DH_)       // 4096
#define NO_  (HH * DH_)           // 2048
#define ROWS (BB * SS)            // 4096

// ---------------- scratch (device globals; no allocation allowed) ----------
__device__ float g_q  [ROWS * (size_t)NQ_];
__device__ float g_ckv[ROWS * (size_t)LAT_];
__device__ float g_kv [ROWS * (size_t)NKV_];
__device__ float g_kr [ROWS * (size_t)DR_];
__device__ float g_att[ROWS * (size_t)NO_];

// bf16 hi/lo splits (activations row-major [M,K]; weights transposed [N,K])
__device__ __align__(16) __nv_bfloat16 g_xh  [ROWS * (size_t)DIM_];
__device__ __align__(16) __nv_bfloat16 g_xl  [ROWS * (size_t)DIM_];
__device__ __align__(16) __nv_bfloat16 g_ckvh[ROWS * (size_t)LAT_];
__device__ __align__(16) __nv_bfloat16 g_ckvl[ROWS * (size_t)LAT_];
__device__ __align__(16) __nv_bfloat16 g_atth[ROWS * (size_t)NO_];
__device__ __align__(16) __nv_bfloat16 g_attl[ROWS * (size_t)NO_];
__device__ __align__(16) __nv_bfloat16 g_wqh [NQ_  * (size_t)DIM_];
__device__ __align__(16) __nv_bfloat16 g_wql [NQ_  * (size_t)DIM_];
__device__ __align__(16) __nv_bfloat16 g_wdh [LAT_ * (size_t)DIM_];
__device__ __align__(16) __nv_bfloat16 g_wdl [LAT_ * (size_t)DIM_];
__device__ __align__(16) __nv_bfloat16 g_wuh [NKV_ * (size_t)LAT_];
__device__ __align__(16) __nv_bfloat16 g_wul [NKV_ * (size_t)LAT_];
__device__ __align__(16) __nv_bfloat16 g_woh [DIM_ * (size_t)NO_];
__device__ __align__(16) __nv_bfloat16 g_wol [DIM_ * (size_t)NO_];

// ---------------- PTX helpers (all arch-portable, no 'a' features) --------
__device__ __forceinline__ uint32_t smem_u32(const void* p) {
    uint32_t a;
    asm("{ .reg .u64 t; cvta.to.shared.u64 t, %1; cvt.u32.u64 %0, t; }"
        : "=r"(a) : "l"(p));
    return a;
}
__device__ __forceinline__ void cpa16(uint32_t dst, const void* src) {
    asm volatile("cp.async.cg.shared.global [%0], [%1], 16;"
                 :: "r"(dst), "l"(src) : "memory");
}
__device__ __forceinline__ void cpa_commit() {
    asm volatile("cp.async.commit_group;" ::: "memory");
}
__device__ __forceinline__ void cpa_wait1() {
    asm volatile("cp.async.wait_group 1;" ::: "memory");
}
__device__ __forceinline__ void ldmx4(uint32_t* r, uint32_t addr) {
    asm volatile("ldmatrix.sync.aligned.m8n8.x4.shared.b16 {%0,%1,%2,%3}, [%4];"
        : "=r"(r[0]), "=r"(r[1]), "=r"(r[2]), "=r"(r[3]) : "r"(addr));
}
__device__ __forceinline__ void mma16816(float* d, const uint32_t* a, const uint32_t* b) {
    asm volatile(
        "mma.sync.aligned.m16n8k16.row.col.f32.bf16.bf16.f32 "
        "{%0,%1,%2,%3}, {%4,%5,%6,%7}, {%8,%9}, {%0,%1,%2,%3};"
        : "+f"(d[0]), "+f"(d[1]), "+f"(d[2]), "+f"(d[3])
        : "r"(a[0]), "r"(a[1]), "r"(a[2]), "r"(a[3]), "r"(b[0]), "r"(b[1]));
}

// ---------------- elementwise split: v -> hi(bf16), lo(bf16 of v-hi) -------
__global__ __launch_bounds__(256) void split_k(
    const float* __restrict__ A, __nv_bfloat16* __restrict__ h,
    __nv_bfloat16* __restrict__ l, int n4)
{
    int i = blockIdx.x * 256 + threadIdx.x;
    if (i >= n4) return;
    float4 v = *(const float4*)(A + (size_t)i * 4);
    __nv_bfloat16 hx = __float2bfloat16(v.x), hy = __float2bfloat16(v.y);
    __nv_bfloat16 hz = __float2bfloat16(v.z), hw = __float2bfloat16(v.w);
    __nv_bfloat162* hp = (__nv_bfloat162*)(h + (size_t)i * 4);
    hp[0] = __nv_bfloat162(hx, hy);
    hp[1] = __nv_bfloat162(hz, hw);
    __nv_bfloat162* lp = (__nv_bfloat162*)(l + (size_t)i * 4);
    lp[0] = __nv_bfloat162(__float2bfloat16(v.x - __bfloat162float(hx)),
                           __float2bfloat16(v.y - __bfloat162float(hy)));
    lp[1] = __nv_bfloat162(__float2bfloat16(v.z - __bfloat162float(hz)),
                           __float2bfloat16(v.w - __bfloat162float(hw)));
}

// ---------------- transpose + split weights: T[n][k] = B[k][n] -------------
__global__ __launch_bounds__(256) void tsplitw_k(
    const float* __restrict__ B, __nv_bfloat16* __restrict__ Th,
    __nv_bfloat16* __restrict__ Tl, int K, int N)
{
    __shared__ float tile[32][33];
    const int tx = threadIdx.x & 31, ty = threadIdx.x >> 5;
    const int n0 = blockIdx.x * 32, k0 = blockIdx.y * 32;
#pragma unroll
    for (int i = 0; i < 32; i += 8)
        tile[ty + i][tx] = B[(size_t)(k0 + ty + i) * N + n0 + tx];
    __syncthreads();
#pragma unroll
    for (int i = 0; i < 32; i += 8) {
        float v = tile[tx][ty + i];
        __nv_bfloat16 h = __float2bfloat16(v);
        size_t o = (size_t)(n0 + ty + i) * K + k0 + tx;
        Th[o] = h;
        Tl[o] = __float2bfloat16(v - __bfloat162float(h));
    }
}

// ---------------- bf16 split-2 HMMA GEMM: C = alpha * A @ B^T --------------
// Ah/Al: [M,K] bf16; Bh/Bl: [N,K] bf16. Tile 128x128x32, 2-stage cp.async.
// smem row = 32 bf16 = 64B = 4x16B chunks, swizzle chunk ^= (row>>1)&3.
#define STG_A 8192
#define STG   32768
#define GEMM_SMEM (2 * STG)

__global__ __launch_bounds__(256) void gemm_mma(
    const __nv_bfloat16* __restrict__ Ah, const __nv_bfloat16* __restrict__ Al,
    const __nv_bfloat16* __restrict__ Bh, const __nv_bfloat16* __restrict__ Bl,
    float* __restrict__ C, int M, int N, int K, float alpha)
{
    extern __shared__ char smc[];
    const uint32_t sb = smem_u32(smc);
    const int t = threadIdx.x, wid = t >> 5, lane = t & 31;
    const int m0 = blockIdx.y * 128, n0 = blockIdx.x * 128;
    const int wr = (wid & 3) * 32, wc = (wid >> 2) * 64;

    float acc[2][8][4];
#pragma unroll
    for (int a = 0; a < 2; a++)
#pragma unroll
        for (int b = 0; b < 8; b++)
#pragma unroll
            for (int c = 0; c < 4; c++) acc[a][b][c] = 0.f;

    const int lr = t >> 2, lc = t & 3;                 // loader: 64 rows x 4 chunks / iter... (512 pairs over 2 iters)
    const int nk = K >> 5;

    // stage loader
    auto load_stage = [&](int kc, int s) {
        const uint32_t base = sb + s * STG;
#pragma unroll
        for (int i = 0; i < 2; i++) {
            const int idx = t + i * 256;
            const int r = idx >> 2, c = idx & 3;
            const uint32_t sw = (uint32_t)(r * 64 + ((c ^ ((r >> 1) & 3)) * 16));
            const size_t ga = (size_t)(m0 + r) * K + kc * 32 + c * 8;
            const size_t gb = (size_t)(n0 + r) * K + kc * 32 + c * 8;
            cpa16(base + sw,             Ah + ga);
            cpa16(base + STG_A + sw,     Al + ga);
            cpa16(base + 2 * STG_A + sw, Bh + gb);
            cpa16(base + 3 * STG_A + sw, Bl + gb);
        }
        cpa_commit();
    };

    load_stage(0, 0);
    load_stage(1, 1);

    for (int kc = 0; kc < nk; kc++) {
        const int s = kc & 1;
        cpa_wait1();
        __syncthreads();
        const uint32_t base = sb + s * STG;

#pragma unroll
        for (int ks = 0; ks < 2; ks++) {
            // A fragments (hi + lo)
            uint32_t ah[2][4], al[2][4];
#pragma unroll
            for (int mi = 0; mi < 2; mi++) {
                const int r = wr + mi * 16 + (lane & 15);
                const int ch = ks * 2 + (lane >> 4);
                const uint32_t ad = base + r * 64 + ((ch ^ ((r >> 1) & 3)) * 16);
                ldmx4(ah[mi], ad);
                ldmx4(al[mi], ad + STG_A);
            }
            // B fragment pairs, consumed immediately to bound liveness
#pragma unroll
            for (int p = 0; p < 4; p++) {
                const int r = wc + p * 16 + (lane & 7) + ((lane >> 4) << 3);
                const int ch = ks * 2 + ((lane >> 3) & 1);
                const uint32_t bd = base + 2 * STG_A + r * 64 + ((ch ^ ((r >> 1) & 3)) * 16);
                uint32_t bh[4], bl[4];
                ldmx4(bh, bd);
                ldmx4(bl, bd + STG_A);
#pragma unroll
                for (int hh = 0; hh < 2; hh++) {
#pragma unroll
                    for (int mi = 0; mi < 2; mi++) {
                        float* d = acc[mi][p * 2 + hh];
                        mma16816(d, ah[mi], bh + hh * 2);
                        mma16816(d, ah[mi], bl + hh * 2);
                        mma16816(d, al[mi], bh + hh * 2);
                    }
                }
            }
        }
        __syncthreads();
        if (kc + 2 < nk) load_stage(kc + 2, s);
        else cpa_commit();   // keep group accounting aligned
    }

    // epilogue
#pragma unroll
    for (int mi = 0; mi < 2; mi++) {
#pragma unroll
        for (int ni = 0; ni < 8; ni++) {
            const int r0 = m0 + wr + mi * 16 + (lane >> 2);
            const int c0 = n0 + wc + ni * 8 + (lane & 3) * 2;
            float2 v0, v1;
            v0.x = alpha * acc[mi][ni][0]; v0.y = alpha * acc[mi][ni][1];
            v1.x = alpha * acc[mi][ni][2]; v1.y = alpha * acc[mi][ni][3];
            *(float2*)&C[(size_t)r0 * N + c0]       = v0;
            *(float2*)&C[(size_t)(r0 + 8) * N + c0] = v1;
        }
    }
}

// ---------------- fp32 SIMT SGEMM (kept for Wkr, N=64) ----------------
__global__ __launch_bounds__(256) void sgemm_k(
    const float* __restrict__ A, const float* __restrict__ Bm,
    float* __restrict__ C, int M, int N, int K, float alpha)
{
    __shared__ float As[8][132];
    __shared__ float Bs[8][132];
    const int t = threadIdx.x;
    const int ty = t >> 4, tx = t & 15;
    const int m0 = blockIdx.y * 128, n0 = blockIdx.x * 128;
    const int ar = t >> 1, ac = (t & 1) * 4;
    const int br = t >> 5, bc = (t & 31) * 4;

    float acc[8][8];
#pragma unroll
    for (int i = 0; i < 8; i++)
#pragma unroll
        for (int j = 0; j < 8; j++) acc[i][j] = 0.f;

    for (int k0 = 0; k0 < K; k0 += 8) {
        float4 av = *(const float4*)&A[(size_t)(m0 + ar) * K + k0 + ac];
        As[ac + 0][ar] = av.x; As[ac + 1][ar] = av.y;
        As[ac + 2][ar] = av.z; As[ac + 3][ar] = av.w;
        float4 bv = make_float4(0.f, 0.f, 0.f, 0.f);
        if (n0 + bc < N)
            bv = *(const float4*)&Bm[(size_t)(k0 + br) * N + n0 + bc];
        *(float4*)&Bs[br][bc] = bv;
        __syncthreads();
#pragma unroll
        for (int k = 0; k < 8; k++) {
            float a[8], b[8];
            *(float4*)(a)     = *(float4*)&As[k][ty * 8];
            *(float4*)(a + 4) = *(float4*)&As[k][ty * 8 + 4];
            *(float4*)(b)     = *(float4*)&Bs[k][tx * 8];
            *(float4*)(b + 4) = *(float4*)&Bs[k][tx * 8 + 4];
#pragma unroll
            for (int i = 0; i < 8; i++)
#pragma unroll
                for (int j = 0; j < 8; j++) acc[i][j] += a[i] * b[j];
        }
        __syncthreads();
    }
#pragma unroll
    for (int i = 0; i < 8; i++) {
        const int row = m0 + ty * 8 + i;
#pragma unroll
        for (int j = 0; j < 8; j += 4) {
            const int col = n0 + tx * 8 + j;
            if (col < N) {
                float4 v;
                v.x = alpha * acc[i][j + 0];
                v.y = alpha * acc[i][j + 1];
                v.z = alpha * acc[i][j + 2];
                v.w = alpha * acc[i][j + 3];
                *(float4*)&C[(size_t)row * N + col] = v;
            }
        }
    }
}

// ---------------- RoPE ----------------
__global__ void rope_q_k(float* __restrict__ q)
{
    int idx = blockIdx.x * blockDim.x + threadIdx.x;
    if (idx >= ROWS * HH * 32) return;
    int i = idx & 31;
    int h = (idx >> 5) & (HH - 1);
    int row = idx >> 9;
    int pos = row & (SS - 1);
    float inv = powf(10000.0f, -(float)i / 32.0f);
    float ang = (float)pos * inv;
    float s, c; sincosf(ang, &s, &c);
    float* p = q + (size_t)row * NQ_ + h * (DH_ + DR_) + DH_;
    float x1 = p[i], x2 = p[i + 32];
    p[i]      = x1 * c - x2 * s;
    p[i + 32] = x2 * c + x1 * s;
}

__global__ void rope_kr_k(float* __restrict__ kr)
{
    int idx = blockIdx.x * blockDim.x + threadIdx.x;
    if (idx >= ROWS * 32) return;
    int i = idx & 31;
    int row = idx >> 5;
    int pos = row & (SS - 1);
    float inv = powf(10000.0f, -(float)i / 32.0f);
    float ang = (float)pos * inv;
    float s, c; sincosf(ang, &s, &c);
    float* p = kr + (size_t)row * DR_;
    float x1 = p[i], x2 = p[i + 32];
    p[i]      = x1 * c - x2 * s;
    p[i + 32] = x2 * c + x1 * s;
}

// ---------------- flash attention (fp32, causal, online softmax) ----------
#define BQ_  128
#define BK_  64
#define QSTR 196
#define KSTR 196
#define VSTR 132
#define PSTR 68
#define SMEM_ATTN ((BQ_*QSTR + BK_*KSTR + BK_*VSTR + BQ_*PSTR + 3*BQ_) * 4)

__global__ __launch_bounds__(256) void attn_k(
    const float* __restrict__ q, const float* __restrict__ kv,
    const float* __restrict__ kr, float* __restrict__ outb)
{
    extern __shared__ float sm[];
    float* sQ  = sm;
    float* sK  = sQ  + BQ_ * QSTR;
    float* sV  = sK  + BK_ * KSTR;
    float* sP  = sV  + BK_ * VSTR;
    float* sMx = sP  + BQ_ * PSTR;
    float* sL  = sMx + BQ_;
    float* sA  = sL  + BQ_;

    const int t = threadIdx.x;
    const int qt = blockIdx.x, h = blockIdx.y, b = blockIdx.z;
    const int q0 = qt * BQ_;
    const int rowg0 = b * SS + q0;

    for (int idx = t; idx < BQ_ * 48; idx += 256) {
        int r = idx / 48, c4 = (idx % 48) * 4;
        *(float4*)&sQ[r * QSTR + c4] =
            *(const float4*)&q[(size_t)(rowg0 + r) * NQ_ + h * (DH_ + DR_) + c4];
    }
    if (t < BQ_) { sMx[t] = -1e30f; sL[t] = 0.f; }

    const int rg = t >> 5;
    const int c0 = (t & 31) * 4;
    const int ty = t >> 4, tx = t & 15;

    float O[16][4];
#pragma unroll
    for (int i = 0; i < 16; i++)
#pragma unroll
        for (int j = 0; j < 4; j++) O[i][j] = 0.f;

    const int nkt = 2 * qt + 2;
    for (int kt = 0; kt < nkt; kt++) {
        const int k0 = kt * BK_;
        __syncthreads();
        for (int idx = t; idx < BK_ * 32; idx += 256) {
            int r = idx / 32, c4 = (idx % 32) * 4;
            const float* base = &kv[(size_t)(b * SS + k0 + r) * NKV_ + h * 2 * DH_];
            *(float4*)&sK[r * KSTR + c4] = *(const float4*)(base + c4);
            *(float4*)&sV[r * VSTR + c4] = *(const float4*)(base + DH_ + c4);
        }
        for (int idx = t; idx < BK_ * 16; idx += 256) {
            int r = idx / 16, c4 = (idx % 16) * 4;
            *(float4*)&sK[r * KSTR + DH_ + c4] =
                *(const float4*)&kr[(size_t)(b * SS + k0 + r) * DR_ + c4];
        }
        __syncthreads();

        float s[8][4];
#pragma unroll
        for (int i = 0; i < 8; i++)
#pragma unroll
            for (int j = 0; j < 4; j++) s[i][j] = 0.f;

#pragma unroll 2
        for (int k = 0; k < DH_ + DR_; k += 4) {
            float4 a[8], bb[4];
#pragma unroll
            for (int i = 0; i < 8; i++)
                a[i] = *(float4*)&sQ[(ty * 8 + i) * QSTR + k];
#pragma unroll
            for (int j = 0; j < 4; j++)
                bb[j] = *(float4*)&sK[(tx + 16 * j) * KSTR + k];
#pragma unroll
            for (int i = 0; i < 8; i++)
#pragma unroll
                for (int j = 0; j < 4; j++) {
                    s[i][j] += a[i].x * bb[j].x;
                    s[i][j] += a[i].y * bb[j].y;
                    s[i][j] += a[i].z * bb[j].z;
                    s[i][j] += a[i].w * bb[j].w;
                }
        }

#pragma unroll
        for (int i = 0; i < 8; i++) {
            const int lrow = ty * 8 + i;
            const int qrow = q0 + lrow;
            float tm = -1e30f;
#pragma unroll
            for (int j = 0; j < 4; j++) {
                const int kc = k0 + tx + 16 * j;
                if (kc > qrow) s[i][j] = -1e30f;
                tm = fmaxf(tm, s[i][j]);
            }
#pragma unroll
            for (int off = 8; off; off >>= 1)
                tm = fmaxf(tm, __shfl_xor_sync(0xffffffffu, tm, off));
            const float mo = sMx[lrow];
            const float mn = fmaxf(mo, tm);
            float tl = 0.f;
#pragma unroll
            for (int j = 0; j < 4; j++) {
                float p = __expf(s[i][j] - mn);
                s[i][j] = p;
                tl += p;
            }
#pragma unroll
            for (int off = 8; off; off >>= 1)
                tl += __shfl_xor_sync(0xffffffffu, tl, off);
            __syncwarp();
            if (tx == 0) {
                const float al = __expf(mo - mn);
                sA[lrow]  = al;
                sMx[lrow] = mn;
                sL[lrow]  = sL[lrow] * al + tl;
            }
            __syncwarp();
#pragma unroll
            for (int j = 0; j < 4; j++)
                sP[lrow * PSTR + tx + 16 * j] = s[i][j];
        }
        __syncthreads();

#pragma unroll
        for (int i = 0; i < 16; i++) {
            const float al = sA[rg * 16 + i];
            O[i][0] *= al; O[i][1] *= al; O[i][2] *= al; O[i][3] *= al;
        }
#pragma unroll 2
        for (int k = 0; k < BK_; k++) {
            const float4 v4 = *(float4*)&sV[k * VSTR + c0];
#pragma unroll
            for (int i = 0; i < 16; i++) {
                const float p = sP[(rg * 16 + i) * PSTR + k];
                O[i][0] += p * v4.x; O[i][1] += p * v4.y;
                O[i][2] += p * v4.z; O[i][3] += p * v4.w;
            }
        }
    }

#pragma unroll
    for (int i = 0; i < 16; i++) {
        const int lrow = rg * 16 + i;
        const float inv = 1.0f / sL[lrow];
        float4 o;
        o.x = O[i][0] * inv; o.y = O[i][1] * inv;
        o.z = O[i][2] * inv; o.w = O[i][3] * inv;
        *(float4*)&outb[(size_t)(rowg0 + lrow) * NO_ + h * DH_ + c0] = o;
    }
}

// ---------------- launch ----------------
extern "C" void kernel_launch(void* const* d_in, const int* in_sizes, int n_in,
                              void* d_out, int out_size)
{
    const float* x    = (const float*)d_in[0];
    const float* Wq   = (const float*)d_in[1];
    const float* Wdkv = (const float*)d_in[2];
    const float* Wkr  = (const float*)d_in[3];
    const float* Wukv = (const float*)d_in[4];
    const float* Wo   = (const float*)d_in[5];
    float* out = (float*)d_out;

    float* q;    cudaGetSymbolAddress((void**)&q,    g_q);
    float* ckv;  cudaGetSymbolAddress((void**)&ckv,  g_ckv);
    float* kvb;  cudaGetSymbolAddress((void**)&kvb,  g_kv);
    float* kr;   cudaGetSymbolAddress((void**)&kr,   g_kr);
    float* att;  cudaGetSymbolAddress((void**)&att,  g_att);
    __nv_bfloat16 *xh, *xl, *ckvh, *ckvl, *atth, *attl;
    __nv_bfloat16 *wqh, *wql, *wdh, *wdl, *wuh, *wul, *woh, *wol;
    cudaGetSymbolAddress((void**)&xh,   g_xh);
    cudaGetSymbolAddress((void**)&xl,   g_xl);
    cudaGetSymbolAddress((void**)&ckvh, g_ckvh);
    cudaGetSymbolAddress((void**)&ckvl, g_ckvl);
    cudaGetSymbolAddress((void**)&atth, g_atth);
    cudaGetSymbolAddress((void**)&attl, g_attl);
    cudaGetSymbolAddress((void**)&wqh,  g_wqh);
    cudaGetSymbolAddress((void**)&wql,  g_wql);
    cudaGetSymbolAddress((void**)&wdh,  g_wdh);
    cudaGetSymbolAddress((void**)&wdl,  g_wdl);
    cudaGetSymbolAddress((void**)&wuh,  g_wuh);
    cudaGetSymbolAddress((void**)&wul,  g_wul);
    cudaGetSymbolAddress((void**)&woh,  g_woh);
    cudaGetSymbolAddress((void**)&wol,  g_wol);

    const float scale = 1.0f / sqrtf((float)(DH_ + DR_));
    dim3 blk(256);

    // splits
    split_k<<<ROWS * DIM_ / 4 / 256, blk>>>(x, xh, xl, ROWS * DIM_ / 4);
    tsplitw_k<<<dim3(NQ_  / 32, DIM_ / 32), blk>>>(Wq,   wqh, wql, DIM_, NQ_);
    tsplitw_k<<<dim3(LAT_ / 32, DIM_ / 32), blk>>>(Wdkv, wdh, wdl, DIM_, LAT_);
    tsplitw_k<<<dim3(NKV_ / 32, LAT_ / 32), blk>>>(Wukv, wuh, wul, LAT_, NKV_);
    tsplitw_k<<<dim3(DIM_ / 32, NO_  / 32), blk>>>(Wo,   woh, wol, NO_,  DIM_);

    cudaFuncSetAttribute(gemm_mma, cudaFuncAttributeMaxDynamicSharedMemorySize, GEMM_SMEM);

    // q = scale * x @ Wq
    gemm_mma<<<dim3(NQ_ / 128, ROWS / 128), blk, GEMM_SMEM>>>(xh, xl, wqh, wql, q, ROWS, NQ_, DIM_, scale);
    // ckv = x @ Wdkv, then split
    gemm_mma<<<dim3(LAT_ / 128, ROWS / 128), blk, GEMM_SMEM>>>(xh, xl, wdh, wdl, ckv, ROWS, LAT_, DIM_, 1.0f);
    split_k<<<ROWS * LAT_ / 4 / 256, blk>>>(ckv, ckvh, ckvl, ROWS * LAT_ / 4);
    // kr = x @ Wkr  (N=64 -> SIMT)
    sgemm_k<<<dim3(1, ROWS / 128), blk>>>(x, Wkr, kr, ROWS, DR_, DIM_, 1.0f);
    // kv = ckv @ Wukv
    gemm_mma<<<dim3(NKV_ / 128, ROWS / 128), blk, GEMM_SMEM>>>(ckvh, ckvl, wuh, wul, kvb, ROWS, NKV_, LAT_, 1.0f);

    rope_q_k <<<(ROWS * HH * 32 + 255) / 256, blk>>>(q);
    rope_kr_k<<<(ROWS * 32 + 255) / 256, blk>>>(kr);

    cudaFuncSetAttribute(attn_k, cudaFuncAttributeMaxDynamicSharedMemorySize, SMEM_ATTN);
    attn_k<<<dim3(SS / BQ_, HH, BB), blk, SMEM_ATTN>>>(q, kvb, kr, att);

    // out = att @ Wo (att split first)
    split_k<<<ROWS * NO_ / 4 / 256, blk>>>(att, atth, attl, ROWS * NO_ / 4);
    gemm_mma<<<dim3(DIM_ / 128, ROWS / 128), blk, GEMM_SMEM>>>(atth, attl, woh, wol, out, ROWS, DIM_, NO_, 1.0f);
}

// round 4
// speedup vs baseline: 2.5953x; 1.5570x over previous
#include <cuda_runtime.h>
#include <cuda_bf16.h>
#include <math.h>
#include <stdint.h>

// ---------------- problem constants ----------------
#define BB   2
#define SS   2048
#define DIM_ 2048
#define HH   16
#define DH_  128
#define LAT_ 512
#define DR_  64
#define NQ_  (HH * (DH_ + DR_))   // 3072
#define NKV_ (HH * 2 * DH_)       // 4096
#define NO_  (HH * DH_)           // 2048
#define ROWS (BB * SS)            // 4096

// ---------------- scratch (device globals; no allocation allowed) ----------
__device__ float g_q  [ROWS * (size_t)NQ_];
__device__ float g_ckv[ROWS * (size_t)LAT_];
__device__ float g_kv [ROWS * (size_t)NKV_];
__device__ float g_kr [ROWS * (size_t)DR_];

// bf16 hi/lo splits
__device__ __align__(16) __nv_bfloat16 g_xh  [ROWS * (size_t)DIM_];
__device__ __align__(16) __nv_bfloat16 g_xl  [ROWS * (size_t)DIM_];
__device__ __align__(16) __nv_bfloat16 g_ckvh[ROWS * (size_t)LAT_];
__device__ __align__(16) __nv_bfloat16 g_ckvl[ROWS * (size_t)LAT_];
__device__ __align__(16) __nv_bfloat16 g_atth[ROWS * (size_t)NO_];
__device__ __align__(16) __nv_bfloat16 g_attl[ROWS * (size_t)NO_];
__device__ __align__(16) __nv_bfloat16 g_qsh [ROWS * (size_t)NQ_];
__device__ __align__(16) __nv_bfloat16 g_qsl [ROWS * (size_t)NQ_];
__device__ __align__(16) __nv_bfloat16 g_kvh2[ROWS * (size_t)NKV_];
__device__ __align__(16) __nv_bfloat16 g_kvl2[ROWS * (size_t)NKV_];
__device__ __align__(16) __nv_bfloat16 g_krh [ROWS * (size_t)DR_];
__device__ __align__(16) __nv_bfloat16 g_krl [ROWS * (size_t)DR_];
__device__ __align__(16) __nv_bfloat16 g_wqh [NQ_  * (size_t)DIM_];
__device__ __align__(16) __nv_bfloat16 g_wql [NQ_  * (size_t)DIM_];
__device__ __align__(16) __nv_bfloat16 g_wdh [LAT_ * (size_t)DIM_];
__device__ __align__(16) __nv_bfloat16 g_wdl [LAT_ * (size_t)DIM_];
__device__ __align__(16) __nv_bfloat16 g_wuh [NKV_ * (size_t)LAT_];
__device__ __align__(16) __nv_bfloat16 g_wul [NKV_ * (size_t)LAT_];
__device__ __align__(16) __nv_bfloat16 g_woh [DIM_ * (size_t)NO_];
__device__ __align__(16) __nv_bfloat16 g_wol [DIM_ * (size_t)NO_];

// ---------------- PTX helpers (arch-portable) ----------
__device__ __forceinline__ uint32_t smem_u32(const void* p) {
    uint32_t a;
    asm("{ .reg .u64 t; cvta.to.shared.u64 t, %1; cvt.u32.u64 %0, t; }"
        : "=r"(a) : "l"(p));
    return a;
}
__device__ __forceinline__ void cpa16(uint32_t dst, const void* src) {
    asm volatile("cp.async.cg.shared.global [%0], [%1], 16;"
                 :: "r"(dst), "l"(src) : "memory");
}
__device__ __forceinline__ void cpa_commit() {
    asm volatile("cp.async.commit_group;" ::: "memory");
}
__device__ __forceinline__ void cpa_wait1() {
    asm volatile("cp.async.wait_group 1;" ::: "memory");
}
__device__ __forceinline__ void cpa_wait0() {
    asm volatile("cp.async.wait_group 0;" ::: "memory");
}
__device__ __forceinline__ void ldmx4(uint32_t* r, uint32_t addr) {
    asm volatile("ldmatrix.sync.aligned.m8n8.x4.shared.b16 {%0,%1,%2,%3}, [%4];"
        : "=r"(r[0]), "=r"(r[1]), "=r"(r[2]), "=r"(r[3]) : "r"(addr));
}
__device__ __forceinline__ void ldmx4t(uint32_t* r, uint32_t addr) {
    asm volatile("ldmatrix.sync.aligned.m8n8.x4.trans.shared.b16 {%0,%1,%2,%3}, [%4];"
        : "=r"(r[0]), "=r"(r[1]), "=r"(r[2]), "=r"(r[3]) : "r"(addr));
}
__device__ __forceinline__ void mma16816(float* d, const uint32_t* a, const uint32_t* b) {
    asm volatile(
        "mma.sync.aligned.m16n8k16.row.col.f32.bf16.bf16.f32 "
        "{%0,%1,%2,%3}, {%4,%5,%6,%7}, {%8,%9}, {%0,%1,%2,%3};"
        : "+f"(d[0]), "+f"(d[1]), "+f"(d[2]), "+f"(d[3])
        : "r"(a[0]), "r"(a[1]), "r"(a[2]), "r"(a[3]), "r"(b[0]), "r"(b[1]));
}

// ---------------- elementwise split ----------------
__global__ __launch_bounds__(256) void split_k(
    const float* __restrict__ A, __nv_bfloat16* __restrict__ h,
    __nv_bfloat16* __restrict__ l, int n4)
{
    int i = blockIdx.x * 256 + threadIdx.x;
    if (i >= n4) return;
    float4 v = *(const float4*)(A + (size_t)i * 4);
    __nv_bfloat16 hx = __float2bfloat16(v.x), hy = __float2bfloat16(v.y);
    __nv_bfloat16 hz = __float2bfloat16(v.z), hw = __float2bfloat16(v.w);
    __nv_bfloat162* hp = (__nv_bfloat162*)(h + (size_t)i * 4);
    hp[0] = __nv_bfloat162(hx, hy);
    hp[1] = __nv_bfloat162(hz, hw);
    __nv_bfloat162* lp = (__nv_bfloat162*)(l + (size_t)i * 4);
    lp[0] = __nv_bfloat162(__float2bfloat16(v.x - __bfloat162float(hx)),
                           __float2bfloat16(v.y - __bfloat162float(hy)));
    lp[1] = __nv_bfloat162(__float2bfloat16(v.z - __bfloat162float(hz)),
                           __float2bfloat16(v.w - __bfloat162float(hw)));
}

// ---------------- transpose + split weights: T[n][k] = B[k][n] -------------
__global__ __launch_bounds__(256) void tsplitw_k(
    const float* __restrict__ B, __nv_bfloat16* __restrict__ Th,
    __nv_bfloat16* __restrict__ Tl, int K, int N)
{
    __shared__ float tile[32][33];
    const int tx = threadIdx.x & 31, ty = threadIdx.x >> 5;
    const int n0 = blockIdx.x * 32, k0 = blockIdx.y * 32;
#pragma unroll
    for (int i = 0; i < 32; i += 8)
        tile[ty + i][tx] = B[(size_t)(k0 + ty + i) * N + n0 + tx];
    __syncthreads();
#pragma unroll
    for (int i = 0; i < 32; i += 8) {
        float v = tile[tx][ty + i];
        __nv_bfloat16 h = __float2bfloat16(v);
        size_t o = (size_t)(n0 + ty + i) * K + k0 + tx;
        Th[o] = h;
        Tl[o] = __float2bfloat16(v - __bfloat162float(h));
    }
}

// ---------------- bf16 split-2 HMMA GEMM (unchanged from R3) ---------------
#define STG_A 8192
#define STG   32768
#define GEMM_SMEM (2 * STG)

__global__ __launch_bounds__(256) void gemm_mma(
    const __nv_bfloat16* __restrict__ Ah, const __nv_bfloat16* __restrict__ Al,
    const __nv_bfloat16* __restrict__ Bh, const __nv_bfloat16* __restrict__ Bl,
    float* __restrict__ C, int M, int N, int K, float alpha)
{
    extern __shared__ char smc[];
    const uint32_t sb = smem_u32(smc);
    const int t = threadIdx.x, wid = t >> 5, lane = t & 31;
    const int m0 = blockIdx.y * 128, n0 = blockIdx.x * 128;
    const int wr = (wid & 3) * 32, wc = (wid >> 2) * 64;

    float acc[2][8][4];
#pragma unroll
    for (int a = 0; a < 2; a++)
#pragma unroll
        for (int b = 0; b < 8; b++)
#pragma unroll
            for (int c = 0; c < 4; c++) acc[a][b][c] = 0.f;

    const int nk = K >> 5;

    auto load_stage = [&](int kc, int s) {
        const uint32_t base = sb + s * STG;
#pragma unroll
        for (int i = 0; i < 2; i++) {
            const int idx = t + i * 256;
            const int r = idx >> 2, c = idx & 3;
            const uint32_t sw = (uint32_t)(r * 64 + ((c ^ ((r >> 1) & 3)) * 16));
            const size_t ga = (size_t)(m0 + r) * K + kc * 32 + c * 8;
            const size_t gb = (size_t)(n0 + r) * K + kc * 32 + c * 8;
            cpa16(base + sw,             Ah + ga);
            cpa16(base + STG_A + sw,     Al + ga);
            cpa16(base + 2 * STG_A + sw, Bh + gb);
            cpa16(base + 3 * STG_A + sw, Bl + gb);
        }
        cpa_commit();
    };

    load_stage(0, 0);
    load_stage(1, 1);

    for (int kc = 0; kc < nk; kc++) {
        const int s = kc & 1;
        cpa_wait1();
        __syncthreads();
        const uint32_t base = sb + s * STG;

#pragma unroll
        for (int ks = 0; ks < 2; ks++) {
            uint32_t ah[2][4], al[2][4];
#pragma unroll
            for (int mi = 0; mi < 2; mi++) {
                const int r = wr + mi * 16 + (lane & 15);
                const int ch = ks * 2 + (lane >> 4);
                const uint32_t ad = base + r * 64 + ((ch ^ ((r >> 1) & 3)) * 16);
                ldmx4(ah[mi], ad);
                ldmx4(al[mi], ad + STG_A);
            }
#pragma unroll
            for (int p = 0; p < 4; p++) {
                const int r = wc + p * 16 + (lane & 7) + ((lane >> 4) << 3);
                const int ch = ks * 2 + ((lane >> 3) & 1);
                const uint32_t bd = base + 2 * STG_A + r * 64 + ((ch ^ ((r >> 1) & 3)) * 16);
                uint32_t bh[4], bl[4];
                ldmx4(bh, bd);
                ldmx4(bl, bd + STG_A);
#pragma unroll
                for (int hh = 0; hh < 2; hh++) {
#pragma unroll
                    for (int mi = 0; mi < 2; mi++) {
                        float* d = acc[mi][p * 2 + hh];
                        mma16816(d, ah[mi], bh + hh * 2);
                        mma16816(d, ah[mi], bl + hh * 2);
                        mma16816(d, al[mi], bh + hh * 2);
                    }
                }
            }
        }
        __syncthreads();
        if (kc + 2 < nk) load_stage(kc + 2, s);
        else cpa_commit();
    }

#pragma unroll
    for (int mi = 0; mi < 2; mi++) {
#pragma unroll
        for (int ni = 0; ni < 8; ni++) {
            const int r0 = m0 + wr + mi * 16 + (lane >> 2);
            const int c0 = n0 + wc + ni * 8 + (lane & 3) * 2;
            float2 v0, v1;
            v0.x = alpha * acc[mi][ni][0]; v0.y = alpha * acc[mi][ni][1];
            v1.x = alpha * acc[mi][ni][2]; v1.y = alpha * acc[mi][ni][3];
            *(float2*)&C[(size_t)r0 * N + c0]       = v0;
            *(float2*)&C[(size_t)(r0 + 8) * N + c0] = v1;
        }
    }
}

// ---------------- fp32 SIMT SGEMM (kept for Wkr, N=64) ----------------
__global__ __launch_bounds__(256) void sgemm_k(
    const float* __restrict__ A, const float* __restrict__ Bm,
    float* __restrict__ C, int M, int N, int K, float alpha)
{
    __shared__ float As[8][132];
    __shared__ float Bs[8][132];
    const int t = threadIdx.x;
    const int ty = t >> 4, tx = t & 15;
    const int m0 = blockIdx.y * 128, n0 = blockIdx.x * 128;
    const int ar = t >> 1, ac = (t & 1) * 4;
    const int br = t >> 5, bc = (t & 31) * 4;

    float acc[8][8];
#pragma unroll
    for (int i = 0; i < 8; i++)
#pragma unroll
        for (int j = 0; j < 8; j++) acc[i][j] = 0.f;

    for (int k0 = 0; k0 < K; k0 += 8) {
        float4 av = *(const float4*)&A[(size_t)(m0 + ar) * K + k0 + ac];
        As[ac + 0][ar] = av.x; As[ac + 1][ar] = av.y;
        As[ac + 2][ar] = av.z; As[ac + 3][ar] = av.w;
        float4 bv = make_float4(0.f, 0.f, 0.f, 0.f);
        if (n0 + bc < N)
            bv = *(const float4*)&Bm[(size_t)(k0 + br) * N + n0 + bc];
        *(float4*)&Bs[br][bc] = bv;
        __syncthreads();
#pragma unroll
        for (int k = 0; k < 8; k++) {
            float a[8], b[8];
            *(float4*)(a)     = *(float4*)&As[k][ty * 8];
            *(float4*)(a + 4) = *(float4*)&As[k][ty * 8 + 4];
            *(float4*)(b)     = *(float4*)&Bs[k][tx * 8];
            *(float4*)(b + 4) = *(float4*)&Bs[k][tx * 8 + 4];
#pragma unroll
            for (int i = 0; i < 8; i++)
#pragma unroll
                for (int j = 0; j < 8; j++) acc[i][j] += a[i] * b[j];
        }
        __syncthreads();
    }
#pragma unroll
    for (int i = 0; i < 8; i++) {
        const int row = m0 + ty * 8 + i;
#pragma unroll
        for (int j = 0; j < 8; j += 4) {
            const int col = n0 + tx * 8 + j;
            if (col < N) {
                float4 v;
                v.x = alpha * acc[i][j + 0];
                v.y = alpha * acc[i][j + 1];
                v.z = alpha * acc[i][j + 2];
                v.w = alpha * acc[i][j + 3];
                *(float4*)&C[(size_t)row * N + col] = v;
            }
        }
    }
}

// ---------------- RoPE ----------------
__global__ void rope_q_k(float* __restrict__ q)
{
    int idx = blockIdx.x * blockDim.x + threadIdx.x;
    if (idx >= ROWS * HH * 32) return;
    int i = idx & 31;
    int h = (idx >> 5) & (HH - 1);
    int row = idx >> 9;
    int pos = row & (SS - 1);
    float inv = powf(10000.0f, -(float)i / 32.0f);
    float ang = (float)pos * inv;
    float s, c; sincosf(ang, &s, &c);
    float* p = q + (size_t)row * NQ_ + h * (DH_ + DR_) + DH_;
    float x1 = p[i], x2 = p[i + 32];
    p[i]      = x1 * c - x2 * s;
    p[i + 32] = x2 * c + x1 * s;
}

__global__ void rope_kr_k(float* __restrict__ kr)
{
    int idx = blockIdx.x * blockDim.x + threadIdx.x;
    if (idx >= ROWS * 32) return;
    int i = idx & 31;
    int row = idx >> 5;
    int pos = row & (SS - 1);
    float inv = powf(10000.0f, -(float)i / 32.0f);
    float ang = (float)pos * inv;
    float s, c; sincosf(ang, &s, &c);
    float* p = kr + (size_t)row * DR_;
    float x1 = p[i], x2 = p[i + 32];
    p[i]      = x1 * c - x2 * s;
    p[i + 32] = x2 * c + x1 * s;
}

// ---------------- flash attention, split-2 bf16 HMMA ----------------------
// CTA: 128 q-rows x (head, batch); 8 warps x 16 rows; k-tiles of 64.
// Q/K rows: 192 bf16 = 384B = 24 chunks of 16B; V rows: 128 bf16 = 256B = 16 chunks.
// XOR swizzle: phys_chunk = ch ^ (row & 7).
#define ASTR_ 384
#define VSTR_ 256
#define OQH 0
#define OQL 49152
#define OKH 98304
#define OKL 122880
#define OVH 147456
#define OVL 163840
#define ATT_SMEM 180224

__global__ __launch_bounds__(256, 1) void attn_mma(
    const __nv_bfloat16* __restrict__ qh,  const __nv_bfloat16* __restrict__ ql,
    const __nv_bfloat16* __restrict__ kvh, const __nv_bfloat16* __restrict__ kvl,
    const __nv_bfloat16* __restrict__ krh, const __nv_bfloat16* __restrict__ krl,
    __nv_bfloat16* __restrict__ atth, __nv_bfloat16* __restrict__ attl)
{
    extern __shared__ char smc[];
    const uint32_t sb = smem_u32(smc);
    const int t = threadIdx.x, w = t >> 5, lane = t & 31;
    const int qt = gridDim.x - 1 - blockIdx.x;   // heavy tiles first
    const int h = blockIdx.y, b = blockIdx.z;
    const int q0 = qt * 128;
    const int rowg0 = b * SS + q0;
    const int g = lane >> 2, tq = lane & 3;
    const int qr0 = q0 + w * 16 + g;

    // ---- load Q tile (once) ----
#pragma unroll
    for (int it = 0; it < 12; it++) {
        const int idx = t + it * 256;            // 128*24
        const int r = idx / 24, c = idx % 24;
        const uint32_t dst = sb + r * ASTR_ + ((c ^ (r & 7)) * 16);
        const size_t go = (size_t)(rowg0 + r) * NQ_ + h * 192 + c * 8;
        cpa16(dst + OQH, qh + go);
        cpa16(dst + OQL, ql + go);
    }
    cpa_commit();

    float m0 = -1e30f, m1 = -1e30f, l0 = 0.f, l1 = 0.f;
    float oacc[16][4];
#pragma unroll
    for (int i = 0; i < 16; i++)
#pragma unroll
        for (int j = 0; j < 4; j++) oacc[i][j] = 0.f;

    const int nkt = 2 * qt + 2;
    const int wkmax = q0 + w * 16 + 15;

    for (int kt = 0; kt < nkt; kt++) {
        const int k0 = kt * 64;
        // ---- load K (kv-nope || kr-rope) and V tiles ----
#pragma unroll
        for (int it = 0; it < 6; it++) {
            const int idx = t + it * 256;        // 64*24
            const int r = idx / 24, c = idx % 24;
            const uint32_t dst = sb + r * ASTR_ + ((c ^ (r & 7)) * 16);
            const size_t rg = (size_t)(b * SS + k0 + r);
            if (c < 16) {
                const size_t go = rg * NKV_ + h * 256 + c * 8;
                cpa16(dst + OKH, kvh + go);
                cpa16(dst + OKL, kvl + go);
            } else {
                const size_t go = rg * DR_ + (c - 16) * 8;
                cpa16(dst + OKH, krh + go);
                cpa16(dst + OKL, krl + go);
            }
        }
#pragma unroll
        for (int it = 0; it < 4; it++) {
            const int idx = t + it * 256;        // 64*16
            const int r = idx >> 4, c = idx & 15;
            const uint32_t dst = sb + r * VSTR_ + ((c ^ (r & 7)) * 16);
            const size_t go = (size_t)(b * SS + k0 + r) * NKV_ + h * 256 + 128 + c * 8;
            cpa16(dst + OVH, kvh + go);
            cpa16(dst + OVL, kvl + go);
        }
        cpa_commit();
        cpa_wait0();
        __syncthreads();

        if (k0 <= wkmax) {
            // ---- S = Q @ K^T (split-2, 3 passes) ----
            float sacc[8][4];
#pragma unroll
            for (int p = 0; p < 8; p++)
#pragma unroll
                for (int c = 0; c < 4; c++) sacc[p][c] = 0.f;

            for (int kc = 0; kc < 12; kc++) {
                const int ra = w * 16 + (lane & 15);
                const int ca = kc * 2 + (lane >> 4);
                const uint32_t qa = sb + ra * ASTR_ + ((ca ^ (ra & 7)) * 16);
                uint32_t aQh[4], aQl[4];
                ldmx4(aQh, qa + OQH);
                ldmx4(aQl, qa + OQL);
#pragma unroll
                for (int g16 = 0; g16 < 4; g16++) {
                    const int rb = g16 * 16 + (lane & 7) + ((lane >> 4) << 3);
                    const int cb = kc * 2 + ((lane >> 3) & 1);
                    const uint32_t ka = sb + rb * ASTR_ + ((cb ^ (rb & 7)) * 16);
                    uint32_t bKh[4], bKl[4];
                    ldmx4(bKh, ka + OKH);
                    ldmx4(bKl, ka + OKL);
#pragma unroll
                    for (int hh = 0; hh < 2; hh++) {
                        float* d = sacc[g16 * 2 + hh];
                        mma16816(d, aQh, bKh + hh * 2);
                        mma16816(d, aQh, bKl + hh * 2);
                        mma16816(d, aQl, bKh + hh * 2);
                    }
                }
            }

            // ---- causal mask (only diagonal tiles) ----
            if (k0 + 63 > q0 + w * 16) {
#pragma unroll
                for (int p = 0; p < 8; p++) {
                    const int colb = k0 + p * 8 + 2 * tq;
#pragma unroll
                    for (int c = 0; c < 4; c++) {
                        const int col = colb + (c & 1);
                        const int row = qr0 + ((c >> 1) << 3);
                        if (col > row) sacc[p][c] = -1e30f;
                    }
                }
            }

            // ---- online softmax (rows g and g+8; quad reductions) ----
            float t0 = -1e30f, t1 = -1e30f;
#pragma unroll
            for (int p = 0; p < 8; p++) {
                t0 = fmaxf(t0, fmaxf(sacc[p][0], sacc[p][1]));
                t1 = fmaxf(t1, fmaxf(sacc[p][2], sacc[p][3]));
            }
            t0 = fmaxf(t0, __shfl_xor_sync(0xffffffffu, t0, 1));
            t0 = fmaxf(t0, __shfl_xor_sync(0xffffffffu, t0, 2));
            t1 = fmaxf(t1, __shfl_xor_sync(0xffffffffu, t1, 1));
            t1 = fmaxf(t1, __shfl_xor_sync(0xffffffffu, t1, 2));
            const float mn0 = fmaxf(m0, t0), mn1 = fmaxf(m1, t1);
            const float a0 = __expf(m0 - mn0), a1 = __expf(m1 - mn1);
            m0 = mn0; m1 = mn1;
            float s0 = 0.f, s1 = 0.f;
#pragma unroll
            for (int p = 0; p < 8; p++) {
                sacc[p][0] = __expf(sacc[p][0] - m0); s0 += sacc[p][0];
                sacc[p][1] = __expf(sacc[p][1] - m0); s0 += sacc[p][1];
                sacc[p][2] = __expf(sacc[p][2] - m1); s1 += sacc[p][2];
                sacc[p][3] = __expf(sacc[p][3] - m1); s1 += sacc[p][3];
            }
            s0 += __shfl_xor_sync(0xffffffffu, s0, 1);
            s0 += __shfl_xor_sync(0xffffffffu, s0, 2);
            s1 += __shfl_xor_sync(0xffffffffu, s1, 1);
            s1 += __shfl_xor_sync(0xffffffffu, s1, 2);
            l0 = l0 * a0 + s0;
            l1 = l1 * a1 + s1;

            // ---- rescale O ----
#pragma unroll
            for (int nt = 0; nt < 16; nt++) {
                oacc[nt][0] *= a0; oacc[nt][1] *= a0;
                oacc[nt][2] *= a1; oacc[nt][3] *= a1;
            }

            // ---- O += P @ V (split-2, P from registers) ----
#pragma unroll
            for (int kc2 = 0; kc2 < 4; kc2++) {
                uint32_t aPh[4], aPl[4];
#pragma unroll
                for (int u = 0; u < 4; u++) {
                    const float* pp = &sacc[kc2 * 2 + (u >> 1)][(u & 1) * 2];
                    const float p0 = pp[0], p1 = pp[1];
                    __nv_bfloat162 hv = __floats2bfloat162_rn(p0, p1);
                    aPh[u] = *(uint32_t*)&hv;
                    __nv_bfloat162 lv = __floats2bfloat162_rn(
                        p0 - __bfloat162float(hv.x), p1 - __bfloat162float(hv.y));
                    aPl[u] = *(uint32_t*)&lv;
                }
#pragma unroll
                for (int v16 = 0; v16 < 8; v16++) {
                    const int rv = kc2 * 16 + (lane & 7) + (((lane >> 3) & 1) << 3);
                    const int cv = v16 * 2 + (lane >> 4);
                    const uint32_t va = sb + rv * VSTR_ + ((cv ^ (rv & 7)) * 16);
                    uint32_t bVh[4], bVl[4];
                    ldmx4t(bVh, va + OVH);
                    ldmx4t(bVl, va + OVL);
#pragma unroll
                    for (int hh = 0; hh < 2; hh++) {
                        float* d = oacc[v16 * 2 + hh];
                        mma16816(d, aPh, bVh + hh * 2);
                        mma16816(d, aPh, bVl + hh * 2);
                        mma16816(d, aPl, bVh + hh * 2);
                    }
                }
            }
        }
        __syncthreads();
    }

    // ---- epilogue: divide by l, write bf16 hi/lo directly ----
    const float i0 = 1.0f / l0, i1 = 1.0f / l1;
#pragma unroll
    for (int nt = 0; nt < 16; nt++) {
        const size_t base0 = (size_t)(rowg0 + w * 16 + g) * NO_ + h * 128 + nt * 8 + 2 * tq;
        const size_t base1 = base0 + (size_t)8 * NO_;
        float o0 = oacc[nt][0] * i0, o1 = oacc[nt][1] * i0;
        __nv_bfloat162 hv = __floats2bfloat162_rn(o0, o1);
        *(__nv_bfloat162*)(atth + base0) = hv;
        *(__nv_bfloat162*)(attl + base0) = __floats2bfloat162_rn(
            o0 - __bfloat162float(hv.x), o1 - __bfloat162float(hv.y));
        float o2 = oacc[nt][2] * i1, o3 = oacc[nt][3] * i1;
        __nv_bfloat162 hv2 = __floats2bfloat162_rn(o2, o3);
        *(__nv_bfloat162*)(atth + base1) = hv2;
        *(__nv_bfloat162*)(attl + base1) = __floats2bfloat162_rn(
            o2 - __bfloat162float(hv2.x), o3 - __bfloat162float(hv2.y));
    }
}

// ---------------- launch ----------------
extern "C" void kernel_launch(void* const* d_in, const int* in_sizes, int n_in,
                              void* d_out, int out_size)
{
    const float* x    = (const float*)d_in[0];
    const float* Wq   = (const float*)d_in[1];
    const float* Wdkv = (const float*)d_in[2];
    const float* Wkr  = (const float*)d_in[3];
    const float* Wukv = (const float*)d_in[4];
    const float* Wo   = (const float*)d_in[5];
    float* out = (float*)d_out;

    float* q;    cudaGetSymbolAddress((void**)&q,    g_q);
    float* ckv;  cudaGetSymbolAddress((void**)&ckv,  g_ckv);
    float* kvb;  cudaGetSymbolAddress((void**)&kvb,  g_kv);
    float* kr;   cudaGetSymbolAddress((void**)&kr,   g_kr);
    __nv_bfloat16 *xh, *xl, *ckvh, *ckvl, *atth, *attl;
    __nv_bfloat16 *qsh, *qsl, *kvh2, *kvl2, *krh, *krl;
    __nv_bfloat16 *wqh, *wql, *wdh, *wdl, *wuh, *wul, *woh, *wol;
    cudaGetSymbolAddress((void**)&xh,   g_xh);
    cudaGetSymbolAddress((void**)&xl,   g_xl);
    cudaGetSymbolAddress((void**)&ckvh, g_ckvh);
    cudaGetSymbolAddress((void**)&ckvl, g_ckvl);
    cudaGetSymbolAddress((void**)&atth, g_atth);
    cudaGetSymbolAddress((void**)&attl, g_attl);
    cudaGetSymbolAddress((void**)&qsh,  g_qsh);
    cudaGetSymbolAddress((void**)&qsl,  g_qsl);
    cudaGetSymbolAddress((void**)&kvh2, g_kvh2);
    cudaGetSymbolAddress((void**)&kvl2, g_kvl2);
    cudaGetSymbolAddress((void**)&krh,  g_krh);
    cudaGetSymbolAddress((void**)&krl,  g_krl);
    cudaGetSymbolAddress((void**)&wqh,  g_wqh);
    cudaGetSymbolAddress((void**)&wql,  g_wql);
    cudaGetSymbolAddress((void**)&wdh,  g_wdh);
    cudaGetSymbolAddress((void**)&wdl,  g_wdl);
    cudaGetSymbolAddress((void**)&wuh,  g_wuh);
    cudaGetSymbolAddress((void**)&wul,  g_wul);
    cudaGetSymbolAddress((void**)&woh,  g_woh);
    cudaGetSymbolAddress((void**)&wol,  g_wol);

    const float scale = 1.0f / sqrtf((float)(DH_ + DR_));
    dim3 blk(256);

    // splits of inputs/weights
    split_k<<<ROWS * DIM_ / 4 / 256, blk>>>(x, xh, xl, ROWS * DIM_ / 4);
    tsplitw_k<<<dim3(NQ_  / 32, DIM_ / 32), blk>>>(Wq,   wqh, wql, DIM_, NQ_);
    tsplitw_k<<<dim3(LAT_ / 32, DIM_ / 32), blk>>>(Wdkv, wdh, wdl, DIM_, LAT_);
    tsplitw_k<<<dim3(NKV_ / 32, LAT_ / 32), blk>>>(Wukv, wuh, wul, LAT_, NKV_);
    tsplitw_k<<<dim3(DIM_ / 32, NO_  / 32), blk>>>(Wo,   woh, wol, NO_,  DIM_);

    cudaFuncSetAttribute(gemm_mma, cudaFuncAttributeMaxDynamicSharedMemorySize, GEMM_SMEM);

    // projections
    gemm_mma<<<dim3(NQ_ / 128, ROWS / 128), blk, GEMM_SMEM>>>(xh, xl, wqh, wql, q, ROWS, NQ_, DIM_, scale);
    gemm_mma<<<dim3(LAT_ / 128, ROWS / 128), blk, GEMM_SMEM>>>(xh, xl, wdh, wdl, ckv, ROWS, LAT_, DIM_, 1.0f);
    split_k<<<ROWS * LAT_ / 4 / 256, blk>>>(ckv, ckvh, ckvl, ROWS * LAT_ / 4);
    sgemm_k<<<dim3(1, ROWS / 128), blk>>>(x, Wkr, kr, ROWS, DR_, DIM_, 1.0f);
    gemm_mma<<<dim3(NKV_ / 128, ROWS / 128), blk, GEMM_SMEM>>>(ckvh, ckvl, wuh, wul, kvb, ROWS, NKV_, LAT_, 1.0f);

    // rope, then split attention operands to bf16 hi/lo
    rope_q_k <<<(ROWS * HH * 32 + 255) / 256, blk>>>(q);
    rope_kr_k<<<(ROWS * 32 + 255) / 256, blk>>>(kr);
    split_k<<<ROWS * NQ_  / 4 / 256, blk>>>(q,   qsh,  qsl,  ROWS * NQ_  / 4);
    split_k<<<ROWS * DR_  / 4 / 256, blk>>>(kr,  krh,  krl,  ROWS * DR_  / 4);
    split_k<<<ROWS * NKV_ / 4 / 256, blk>>>(kvb, kvh2, kvl2, ROWS * NKV_ / 4);

    // attention (HMMA)
    cudaFuncSetAttribute(attn_mma, cudaFuncAttributeMaxDynamicSharedMemorySize, ATT_SMEM);
    attn_mma<<<dim3(SS / 128, HH, BB), blk, ATT_SMEM>>>(qsh, qsl, kvh2, kvl2, krh, krl, atth, attl);

    // out = att @ Wo
    gemm_mma<<<dim3(DIM_ / 128, ROWS / 128), blk, GEMM_SMEM>>>(atth, attl, woh, wol, out, ROWS, DIM_, NO_, 1.0f);
}

// round 5
// speedup vs baseline: 3.3830x; 1.3035x over previous
#include <cuda_runtime.h>
#include <cuda_bf16.h>
#include <math.h>
#include <stdint.h>

// ---------------- problem constants ----------------
#define BB   2
#define SS   2048
#define DIM_ 2048
#define HH   16
#define DH_  128
#define LAT_ 512
#define DR_  64
#define NQ_  (HH * (DH_ + DR_))   // 3072
#define QS_  3200                 // combined q||kr||pad stride (25 tiles of 128)
#define NKV_ (HH * 2 * DH_)       // 4096
#define NO_  (HH * DH_)           // 2048
#define ROWS (BB * SS)            // 4096

// ---------------- scratch (device globals; no allocation allowed) ----------
// bf16 hi/lo pairs everywhere; no fp32 intermediates.
__device__ __align__(16) __nv_bfloat16 g_xh   [ROWS * (size_t)DIM_];
__device__ __align__(16) __nv_bfloat16 g_xl   [ROWS * (size_t)DIM_];
__device__ __align__(16) __nv_bfloat16 g_qkrh [ROWS * (size_t)QS_];
__device__ __align__(16) __nv_bfloat16 g_qkrl [ROWS * (size_t)QS_];
__device__ __align__(16) __nv_bfloat16 g_ckvh [ROWS * (size_t)LAT_];
__device__ __align__(16) __nv_bfloat16 g_ckvl [ROWS * (size_t)LAT_];
__device__ __align__(16) __nv_bfloat16 g_kvh  [ROWS * (size_t)NKV_];
__device__ __align__(16) __nv_bfloat16 g_kvl  [ROWS * (size_t)NKV_];
__device__ __align__(16) __nv_bfloat16 g_atth [ROWS * (size_t)NO_];
__device__ __align__(16) __nv_bfloat16 g_attl [ROWS * (size_t)NO_];
// weights transposed+split: combined [Wq*scale | Wkr | 0] is QS_ x DIM_
__device__ __align__(16) __nv_bfloat16 g_wqkh [QS_  * (size_t)DIM_];
__device__ __align__(16) __nv_bfloat16 g_wqkl [QS_  * (size_t)DIM_];
__device__ __align__(16) __nv_bfloat16 g_wdh  [LAT_ * (size_t)DIM_];
__device__ __align__(16) __nv_bfloat16 g_wdl  [LAT_ * (size_t)DIM_];
__device__ __align__(16) __nv_bfloat16 g_wuh  [NKV_ * (size_t)LAT_];
__device__ __align__(16) __nv_bfloat16 g_wul  [NKV_ * (size_t)LAT_];
__device__ __align__(16) __nv_bfloat16 g_woh  [DIM_ * (size_t)NO_];
__device__ __align__(16) __nv_bfloat16 g_wol  [DIM_ * (size_t)NO_];

// ---------------- PTX helpers (arch-portable) ----------
__device__ __forceinline__ uint32_t smem_u32(const void* p) {
    uint32_t a;
    asm("{ .reg .u64 t; cvta.to.shared.u64 t, %1; cvt.u32.u64 %0, t; }"
        : "=r"(a) : "l"(p));
    return a;
}
__device__ __forceinline__ void cpa16(uint32_t dst, const void* src) {
    asm volatile("cp.async.cg.shared.global [%0], [%1], 16;"
                 :: "r"(dst), "l"(src) : "memory");
}
__device__ __forceinline__ void cpa_commit() {
    asm volatile("cp.async.commit_group;" ::: "memory");
}
__device__ __forceinline__ void cpa_wait0() {
    asm volatile("cp.async.wait_group 0;" ::: "memory");
}
__device__ __forceinline__ void cpa_wait2() {
    asm volatile("cp.async.wait_group 2;" ::: "memory");
}
__device__ __forceinline__ void ldmx4(uint32_t* r, uint32_t addr) {
    asm volatile("ldmatrix.sync.aligned.m8n8.x4.shared.b16 {%0,%1,%2,%3}, [%4];"
        : "=r"(r[0]), "=r"(r[1]), "=r"(r[2]), "=r"(r[3]) : "r"(addr));
}
__device__ __forceinline__ void ldmx4t(uint32_t* r, uint32_t addr) {
    asm volatile("ldmatrix.sync.aligned.m8n8.x4.trans.shared.b16 {%0,%1,%2,%3}, [%4];"
        : "=r"(r[0]), "=r"(r[1]), "=r"(r[2]), "=r"(r[3]) : "r"(addr));
}
__device__ __forceinline__ void mma16816(float* d, const uint32_t* a, const uint32_t* b) {
    asm volatile(
        "mma.sync.aligned.m16n8k16.row.col.f32.bf16.bf16.f32 "
        "{%0,%1,%2,%3}, {%4,%5,%6,%7}, {%8,%9}, {%0,%1,%2,%3};"
        : "+f"(d[0]), "+f"(d[1]), "+f"(d[2]), "+f"(d[3])
        : "r"(a[0]), "r"(a[1]), "r"(a[2]), "r"(a[3]), "r"(b[0]), "r"(b[1]));
}

// ---------------- elementwise split (x only) ----------------
__global__ __launch_bounds__(256) void split_k(
    const float* __restrict__ A, __nv_bfloat16* __restrict__ h,
    __nv_bfloat16* __restrict__ l, int n4)
{
    int i = blockIdx.x * 256 + threadIdx.x;
    if (i >= n4) return;
    float4 v = *(const float4*)(A + (size_t)i * 4);
    __nv_bfloat16 hx = __float2bfloat16(v.x), hy = __float2bfloat16(v.y);
    __nv_bfloat16 hz = __float2bfloat16(v.z), hw = __float2bfloat16(v.w);
    __nv_bfloat162* hp = (__nv_bfloat162*)(h + (size_t)i * 4);
    hp[0] = __nv_bfloat162(hx, hy);
    hp[1] = __nv_bfloat162(hz, hw);
    __nv_bfloat162* lp = (__nv_bfloat162*)(l + (size_t)i * 4);
    lp[0] = __nv_bfloat162(__float2bfloat16(v.x - __bfloat162float(hx)),
                           __float2bfloat16(v.y - __bfloat162float(hy)));
    lp[1] = __nv_bfloat162(__float2bfloat16(v.z - __bfloat162float(hz)),
                           __float2bfloat16(v.w - __bfloat162float(hw)));
}

// ---------------- transpose + split weights: T[n][k] = alpha*B[k][n] -------
__global__ __launch_bounds__(256) void tsplitw_k(
    const float* __restrict__ B, __nv_bfloat16* __restrict__ Th,
    __nv_bfloat16* __restrict__ Tl, int K, int N, float alpha)
{
    __shared__ float tile[32][33];
    const int tx = threadIdx.x & 31, ty = threadIdx.x >> 5;
    const int n0 = blockIdx.x * 32, k0 = blockIdx.y * 32;
#pragma unroll
    for (int i = 0; i < 32; i += 8)
        tile[ty + i][tx] = B[(size_t)(k0 + ty + i) * N + n0 + tx];
    __syncthreads();
#pragma unroll
    for (int i = 0; i < 32; i += 8) {
        float v = alpha * tile[tx][ty + i];
        __nv_bfloat16 h = __float2bfloat16(v);
        size_t o = (size_t)(n0 + ty + i) * K + k0 + tx;
        Th[o] = h;
        Tl[o] = __float2bfloat16(v - __bfloat162float(h));
    }
}

// zero-pad kernel (pad rows of combined weight)
__global__ void zpad_k(__nv_bfloat16* __restrict__ h, __nv_bfloat16* __restrict__ l, int n)
{
    int i = blockIdx.x * 256 + threadIdx.x;
    if (i < n) { h[i] = __float2bfloat16(0.f); l[i] = __float2bfloat16(0.f); }
}

// ---------------- bf16 split-2 HMMA GEMM, 3-stage, fused hi/lo epilogue ----
#define STG_A 8192
#define STG   32768
#define GEMM_SMEM (3 * STG)

__global__ __launch_bounds__(256) void gemm_mma(
    const __nv_bfloat16* __restrict__ Ah, const __nv_bfloat16* __restrict__ Al,
    const __nv_bfloat16* __restrict__ Bh, const __nv_bfloat16* __restrict__ Bl,
    float* __restrict__ C, __nv_bfloat16* __restrict__ Ch,
    __nv_bfloat16* __restrict__ Cl, int M, int N, int K, int out_hl)
{
    extern __shared__ char smc[];
    const uint32_t sb = smem_u32(smc);
    const int t = threadIdx.x, wid = t >> 5, lane = t & 31;
    const int m0 = blockIdx.y * 128, n0 = blockIdx.x * 128;
    const int wr = (wid & 3) * 32, wc = (wid >> 2) * 64;

    float acc[2][8][4];
#pragma unroll
    for (int a = 0; a < 2; a++)
#pragma unroll
        for (int b = 0; b < 8; b++)
#pragma unroll
            for (int c = 0; c < 4; c++) acc[a][b][c] = 0.f;

    const int nk = K >> 5;

    auto load_stage = [&](int kc, int s) {
        const uint32_t base = sb + s * STG;
#pragma unroll
        for (int i = 0; i < 2; i++) {
            const int idx = t + i * 256;
            const int r = idx >> 2, c = idx & 3;
            const uint32_t sw = (uint32_t)(r * 64 + ((c ^ ((r >> 1) & 3)) * 16));
            const size_t ga = (size_t)(m0 + r) * K + kc * 32 + c * 8;
            const size_t gb = (size_t)(n0 + r) * K + kc * 32 + c * 8;
            cpa16(base + sw,             Ah + ga);
            cpa16(base + STG_A + sw,     Al + ga);
            cpa16(base + 2 * STG_A + sw, Bh + gb);
            cpa16(base + 3 * STG_A + sw, Bl + gb);
        }
        cpa_commit();
    };

    load_stage(0, 0);
    load_stage(1, 1);
    load_stage(2, 2);

    int s = 0;
    for (int kc = 0; kc < nk; kc++) {
        cpa_wait2();
        __syncthreads();
        const uint32_t base = sb + s * STG;

#pragma unroll
        for (int ks = 0; ks < 2; ks++) {
            uint32_t ah[2][4], al[2][4];
#pragma unroll
            for (int mi = 0; mi < 2; mi++) {
                const int r = wr + mi * 16 + (lane & 15);
                const int ch = ks * 2 + (lane >> 4);
                const uint32_t ad = base + r * 64 + ((ch ^ ((r >> 1) & 3)) * 16);
                ldmx4(ah[mi], ad);
                ldmx4(al[mi], ad + STG_A);
            }
#pragma unroll
            for (int p = 0; p < 4; p++) {
                const int r = wc + p * 16 + (lane & 7) + ((lane >> 4) << 3);
                const int ch = ks * 2 + ((lane >> 3) & 1);
                const uint32_t bd = base + 2 * STG_A + r * 64 + ((ch ^ ((r >> 1) & 3)) * 16);
                uint32_t bh[4], bl[4];
                ldmx4(bh, bd);
                ldmx4(bl, bd + STG_A);
#pragma unroll
                for (int hh = 0; hh < 2; hh++) {
#pragma unroll
                    for (int mi = 0; mi < 2; mi++) {
                        float* d = acc[mi][p * 2 + hh];
                        mma16816(d, ah[mi], bh + hh * 2);
                        mma16816(d, ah[mi], bl + hh * 2);
                        mma16816(d, al[mi], bh + hh * 2);
                    }
                }
            }
        }
        __syncthreads();
        if (kc + 3 < nk) load_stage(kc + 3, s);
        else cpa_commit();
        s = (s == 2) ? 0 : s + 1;
    }

    // epilogue
#pragma unroll
    for (int mi = 0; mi < 2; mi++) {
#pragma unroll
        for (int ni = 0; ni < 8; ni++) {
            const int r0 = m0 + wr + mi * 16 + (lane >> 2);
            const int c0 = n0 + wc + ni * 8 + (lane & 3) * 2;
            if (out_hl) {
#pragma unroll
                for (int half = 0; half < 2; half++) {
                    const size_t o = (size_t)(r0 + half * 8) * N + c0;
                    const float v0 = acc[mi][ni][half * 2 + 0];
                    const float v1 = acc[mi][ni][half * 2 + 1];
                    __nv_bfloat162 hv = __floats2bfloat162_rn(v0, v1);
                    *(__nv_bfloat162*)(Ch + o) = hv;
                    *(__nv_bfloat162*)(Cl + o) = __floats2bfloat162_rn(
                        v0 - __bfloat162float(hv.x), v1 - __bfloat162float(hv.y));
                }
            } else {
                float2 v0, v1;
                v0.x = acc[mi][ni][0]; v0.y = acc[mi][ni][1];
                v1.x = acc[mi][ni][2]; v1.y = acc[mi][ni][3];
                *(float2*)&C[(size_t)r0 * N + c0]       = v0;
                *(float2*)&C[(size_t)(r0 + 8) * N + c0] = v1;
            }
        }
    }
}

// ---------------- RoPE in hi/lo domain (q rope blocks + kr block) ---------
// u in [0,16): q head u, cols u*192+128 .. +191; u==16: kr at col 3072.
__global__ void rope_hl(__nv_bfloat16* __restrict__ h, __nv_bfloat16* __restrict__ l)
{
    int idx = blockIdx.x * blockDim.x + threadIdx.x;   // ROWS*17*32
    if (idx >= ROWS * 17 * 32) return;
    int i   = idx & 31;
    int u   = (idx >> 5) % 17;
    int row = (idx >> 5) / 17;
    int pos = row & (SS - 1);
    float inv = powf(10000.0f, -(float)i / 32.0f);
    float ang = (float)pos * inv;
    float s, c; sincosf(ang, &s, &c);
    size_t base = (size_t)row * QS_ + (u < 16 ? u * 192 + 128 : 3072);
    float x1 = __bfloat162float(h[base + i])      + __bfloat162float(l[base + i]);
    float x2 = __bfloat162float(h[base + i + 32]) + __bfloat162float(l[base + i + 32]);
    float r1 = x1 * c - x2 * s;
    float r2 = x2 * c + x1 * s;
    __nv_bfloat16 h1 = __float2bfloat16(r1), h2 = __float2bfloat16(r2);
    h[base + i]      = h1;
    l[base + i]      = __float2bfloat16(r1 - __bfloat162float(h1));
    h[base + i + 32] = h2;
    l[base + i + 32] = __float2bfloat16(r2 - __bfloat162float(h2));
}

// ---------------- flash attention, split-2 bf16 HMMA, overlapped loads ----
#define ASTR_ 384
#define VSTR_ 256
#define OQH 0
#define OQL 49152
#define OKH 98304
#define OKL 122880
#define OVH 147456
#define OVL 163840
#define ATT_SMEM 180224

__global__ __launch_bounds__(256, 1) void attn_mma(
    const __nv_bfloat16* __restrict__ qh,  const __nv_bfloat16* __restrict__ ql,
    const __nv_bfloat16* __restrict__ kvh, const __nv_bfloat16* __restrict__ kvl,
    __nv_bfloat16* __restrict__ atth, __nv_bfloat16* __restrict__ attl)
{
    extern __shared__ char smc[];
    const uint32_t sb = smem_u32(smc);
    const int t = threadIdx.x, w = t >> 5, lane = t & 31;
    const int qt = gridDim.x - 1 - blockIdx.x;   // heavy tiles first
    const int h = blockIdx.y, b = blockIdx.z;
    const int q0 = qt * 128;
    const int rowg0 = b * SS + q0;
    const int g = lane >> 2, tq = lane & 3;
    const int qr0 = q0 + w * 16 + g;

    auto loadK = [&](int kt) {
        const int k0 = kt * 64;
#pragma unroll
        for (int it = 0; it < 6; it++) {
            const int idx = t + it * 256;        // 64*24
            const int r = idx / 24, c = idx % 24;
            const uint32_t dst = sb + r * ASTR_ + ((c ^ (r & 7)) * 16);
            const size_t rg = (size_t)(b * SS + k0 + r);
            if (c < 16) {
                const size_t go = rg * NKV_ + h * 256 + c * 8;
                cpa16(dst + OKH, kvh + go);
                cpa16(dst + OKL, kvl + go);
            } else {
                const size_t go = rg * QS_ + 3072 + (c - 16) * 8;
                cpa16(dst + OKH, qh + go);
                cpa16(dst + OKL, ql + go);
            }
        }
        cpa_commit();
    };
    auto loadV = [&](int kt) {
        const int k0 = kt * 64;
#pragma unroll
        for (int it = 0; it < 4; it++) {
            const int idx = t + it * 256;        // 64*16
            const int r = idx >> 4, c = idx & 15;
            const uint32_t dst = sb + r * VSTR_ + ((c ^ (r & 7)) * 16);
            const size_t go = (size_t)(b * SS + k0 + r) * NKV_ + h * 256 + 128 + c * 8;
            cpa16(dst + OVH, kvh + go);
            cpa16(dst + OVL, kvl + go);
        }
        cpa_commit();
    };

    // ---- prologue: Q tile + K(0) ----
#pragma unroll
    for (int it = 0; it < 12; it++) {
        const int idx = t + it * 256;            // 128*24
        const int r = idx / 24, c = idx % 24;
        const uint32_t dst = sb + r * ASTR_ + ((c ^ (r & 7)) * 16);
        const size_t go = (size_t)(rowg0 + r) * QS_ + h * 192 + c * 8;
        cpa16(dst + OQH, qh + go);
        cpa16(dst + OQL, ql + go);
    }
    cpa_commit();
    loadK(0);

    float m0 = -1e30f, m1 = -1e30f, l0 = 0.f, l1 = 0.f;
    float oacc[16][4];
#pragma unroll
    for (int i = 0; i < 16; i++)
#pragma unroll
        for (int j = 0; j < 4; j++) oacc[i][j] = 0.f;

    const int nkt = 2 * qt + 2;
    const int wkmax = q0 + w * 16 + 15;

    for (int kt = 0; kt < nkt; kt++) {
        const int k0 = kt * 64;
        cpa_wait0();          // K(kt) (and Q on first iter) resident
        __syncthreads();      // prior PV done -> V buffer free
        loadV(kt);            // V(kt) overlaps QK compute

        const bool active = (k0 <= wkmax);
        float sacc[8][4];
        if (active) {
            // ---- S = Q @ K^T (split-2, 3 passes) ----
#pragma unroll
            for (int p = 0; p < 8; p++)
#pragma unroll
                for (int c = 0; c < 4; c++) sacc[p][c] = 0.f;

            for (int kc = 0; kc < 12; kc++) {
                const int ra = w * 16 + (lane & 15);
                const int ca = kc * 2 + (lane >> 4);
                const uint32_t qa = sb + ra * ASTR_ + ((ca ^ (ra & 7)) * 16);
                uint32_t aQh[4], aQl[4];
                ldmx4(aQh, qa + OQH);
                ldmx4(aQl, qa + OQL);
#pragma unroll
                for (int g16 = 0; g16 < 4; g16++) {
                    const int rb = g16 * 16 + (lane & 7) + ((lane >> 4) << 3);
                    const int cb = kc * 2 + ((lane >> 3) & 1);
                    const uint32_t ka = sb + rb * ASTR_ + ((cb ^ (rb & 7)) * 16);
                    uint32_t bKh[4], bKl[4];
                    ldmx4(bKh, ka + OKH);
                    ldmx4(bKl, ka + OKL);
#pragma unroll
                    for (int hh = 0; hh < 2; hh++) {
                        float* d = sacc[g16 * 2 + hh];
                        mma16816(d, aQh, bKh + hh * 2);
                        mma16816(d, aQh, bKl + hh * 2);
                        mma16816(d, aQl, bKh + hh * 2);
                    }
                }
            }
        }

        cpa_wait0();          // V(kt) resident
        __syncthreads();      // all warps done with K(kt)
        if (kt + 1 < nkt) loadK(kt + 1);   // overlaps softmax + PV

        if (active) {
            // ---- causal mask (diagonal tiles only) ----
            if (k0 + 63 > q0 + w * 16) {
#pragma unroll
                for (int p = 0; p < 8; p++) {
                    const int colb = k0 + p * 8 + 2 * tq;
#pragma unroll
                    for (int c = 0; c < 4; c++) {
                        const int col = colb + (c & 1);
                        const int row = qr0 + ((c >> 1) << 3);
                        if (col > row) sacc[p][c] = -1e30f;
                    }
                }
            }

            // ---- online softmax ----
            float t0 = -1e30f, t1 = -1e30f;
#pragma unroll
            for (int p = 0; p < 8; p++) {
                t0 = fmaxf(t0, fmaxf(sacc[p][0], sacc[p][1]));
                t1 = fmaxf(t1, fmaxf(sacc[p][2], sacc[p][3]));
            }
            t0 = fmaxf(t0, __shfl_xor_sync(0xffffffffu, t0, 1));
            t0 = fmaxf(t0, __shfl_xor_sync(0xffffffffu, t0, 2));
            t1 = fmaxf(t1, __shfl_xor_sync(0xffffffffu, t1, 1));
            t1 = fmaxf(t1, __shfl_xor_sync(0xffffffffu, t1, 2));
            const float mn0 = fmaxf(m0, t0), mn1 = fmaxf(m1, t1);
            const float a0 = __expf(m0 - mn0), a1 = __expf(m1 - mn1);
            m0 = mn0; m1 = mn1;
            float s0 = 0.f, s1 = 0.f;
#pragma unroll
            for (int p = 0; p < 8; p++) {
                sacc[p][0] = __expf(sacc[p][0] - m0); s0 += sacc[p][0];
                sacc[p][1] = __expf(sacc[p][1] - m0); s0 += sacc[p][1];
                sacc[p][2] = __expf(sacc[p][2] - m1); s1 += sacc[p][2];
                sacc[p][3] = __expf(sacc[p][3] - m1); s1 += sacc[p][3];
            }
            s0 += __shfl_xor_sync(0xffffffffu, s0, 1);
            s0 += __shfl_xor_sync(0xffffffffu, s0, 2);
            s1 += __shfl_xor_sync(0xffffffffu, s1, 1);
            s1 += __shfl_xor_sync(0xffffffffu, s1, 2);
            l0 = l0 * a0 + s0;
            l1 = l1 * a1 + s1;

#pragma unroll
            for (int nt = 0; nt < 16; nt++) {
                oacc[nt][0] *= a0; oacc[nt][1] *= a0;
                oacc[nt][2] *= a1; oacc[nt][3] *= a1;
            }

            // ---- O += P @ V (split-2, P from registers) ----
#pragma unroll
            for (int kc2 = 0; kc2 < 4; kc2++) {
                uint32_t aPh[4], aPl[4];
#pragma unroll
                for (int u = 0; u < 4; u++) {
                    const float* pp = &sacc[kc2 * 2 + (u >> 1)][(u & 1) * 2];
                    const float p0 = pp[0], p1 = pp[1];
                    __nv_bfloat162 hv = __floats2bfloat162_rn(p0, p1);
                    aPh[u] = *(uint32_t*)&hv;
                    __nv_bfloat162 lv = __floats2bfloat162_rn(
                        p0 - __bfloat162float(hv.x), p1 - __bfloat162float(hv.y));
                    aPl[u] = *(uint32_t*)&lv;
                }
#pragma unroll
                for (int v16 = 0; v16 < 8; v16++) {
                    const int rv = kc2 * 16 + (lane & 7) + (((lane >> 3) & 1) << 3);
                    const int cv = v16 * 2 + (lane >> 4);
                    const uint32_t va = sb + rv * VSTR_ + ((cv ^ (rv & 7)) * 16);
                    uint32_t bVh[4], bVl[4];
                    ldmx4t(bVh, va + OVH);
                    ldmx4t(bVl, va + OVL);
#pragma unroll
                    for (int hh = 0; hh < 2; hh++) {
                        float* d = oacc[v16 * 2 + hh];
                        mma16816(d, aPh, bVh + hh * 2);
                        mma16816(d, aPh, bVl + hh * 2);
                        mma16816(d, aPl, bVh + hh * 2);
                    }
                }
            }
        }
    }

    // ---- epilogue: divide by l, write bf16 hi/lo ----
    const float i0 = 1.0f / l0, i1 = 1.0f / l1;
#pragma unroll
    for (int nt = 0; nt < 16; nt++) {
        const size_t base0 = (size_t)(rowg0 + w * 16 + g) * NO_ + h * 128 + nt * 8 + 2 * tq;
        const size_t base1 = base0 + (size_t)8 * NO_;
        float o0 = oacc[nt][0] * i0, o1 = oacc[nt][1] * i0;
        __nv_bfloat162 hv = __floats2bfloat162_rn(o0, o1);
        *(__nv_bfloat162*)(atth + base0) = hv;
        *(__nv_bfloat162*)(attl + base0) = __floats2bfloat162_rn(
            o0 - __bfloat162float(hv.x), o1 - __bfloat162float(hv.y));
        float o2 = oacc[nt][2] * i1, o3 = oacc[nt][3] * i1;
        __nv_bfloat162 hv2 = __floats2bfloat162_rn(o2, o3);
        *(__nv_bfloat162*)(atth + base1) = hv2;
        *(__nv_bfloat162*)(attl + base1) = __floats2bfloat162_rn(
            o2 - __bfloat162float(hv2.x), o3 - __bfloat162float(hv2.y));
    }
}

// ---------------- launch ----------------
extern "C" void kernel_launch(void* const* d_in, const int* in_sizes, int n_in,
                              void* d_out, int out_size)
{
    const float* x    = (const float*)d_in[0];
    const float* Wq   = (const float*)d_in[1];
    const float* Wdkv = (const float*)d_in[2];
    const float* Wkr  = (const float*)d_in[3];
    const float* Wukv = (const float*)d_in[4];
    const float* Wo   = (const float*)d_in[5];
    float* out = (float*)d_out;

    __nv_bfloat16 *xh, *xl, *qkrh, *qkrl, *ckvh, *ckvl, *kvh, *kvl, *atth, *attl;
    __nv_bfloat16 *wqkh, *wqkl, *wdh, *wdl, *wuh, *wul, *woh, *wol;
    cudaGetSymbolAddress((void**)&xh,   g_xh);
    cudaGetSymbolAddress((void**)&xl,   g_xl);
    cudaGetSymbolAddress((void**)&qkrh, g_qkrh);
    cudaGetSymbolAddress((void**)&qkrl, g_qkrl);
    cudaGetSymbolAddress((void**)&ckvh, g_ckvh);
    cudaGetSymbolAddress((void**)&ckvl, g_ckvl);
    cudaGetSymbolAddress((void**)&kvh,  g_kvh);
    cudaGetSymbolAddress((void**)&kvl,  g_kvl);
    cudaGetSymbolAddress((void**)&atth, g_atth);
    cudaGetSymbolAddress((void**)&attl, g_attl);
    cudaGetSymbolAddress((void**)&wqkh, g_wqkh);
    cudaGetSymbolAddress((void**)&wqkl, g_wqkl);
    cudaGetSymbolAddress((void**)&wdh,  g_wdh);
    cudaGetSymbolAddress((void**)&wdl,  g_wdl);
    cudaGetSymbolAddress((void**)&wuh,  g_wuh);
    cudaGetSymbolAddress((void**)&wul,  g_wul);
    cudaGetSymbolAddress((void**)&woh,  g_woh);
    cudaGetSymbolAddress((void**)&wol,  g_wol);

    const float scale = 1.0f / sqrtf((float)(DH_ + DR_));
    dim3 blk(256);

    // input split + weight transpose/splits (scale folded into Wq)
    split_k<<<ROWS * DIM_ / 4 / 256, blk>>>(x, xh, xl, ROWS * DIM_ / 4);
    tsplitw_k<<<dim3(NQ_ / 32, DIM_ / 32), blk>>>(Wq, wqkh, wqkl, DIM_, NQ_, scale);
    tsplitw_k<<<dim3(DR_ / 32, DIM_ / 32), blk>>>(Wkr,
        wqkh + (size_t)NQ_ * DIM_, wqkl + (size_t)NQ_ * DIM_, DIM_, DR_, 1.0f);
    zpad_k<<<(64 * DIM_ + 255) / 256, blk>>>(
        wqkh + (size_t)(NQ_ + DR_) * DIM_, wqkl + (size_t)(NQ_ + DR_) * DIM_, 64 * DIM_);
    tsplitw_k<<<dim3(LAT_ / 32, DIM_ / 32), blk>>>(Wdkv, wdh, wdl, DIM_, LAT_, 1.0f);
    tsplitw_k<<<dim3(NKV_ / 32, LAT_ / 32), blk>>>(Wukv, wuh, wul, LAT_, NKV_, 1.0f);
    tsplitw_k<<<dim3(DIM_ / 32, NO_  / 32), blk>>>(Wo,   woh, wol, NO_,  DIM_, 1.0f);

    cudaFuncSetAttribute(gemm_mma, cudaFuncAttributeMaxDynamicSharedMemorySize, GEMM_SMEM);

    // [q | kr] = x @ [Wq*scale | Wkr]  -> hi/lo
    gemm_mma<<<dim3(QS_ / 128, ROWS / 128), blk, GEMM_SMEM>>>(
        xh, xl, wqkh, wqkl, nullptr, qkrh, qkrl, ROWS, QS_, DIM_, 1);
    // ckv = x @ Wdkv -> hi/lo
    gemm_mma<<<dim3(LAT_ / 128, ROWS / 128), blk, GEMM_SMEM>>>(
        xh, xl, wdh, wdl, nullptr, ckvh, ckvl, ROWS, LAT_, DIM_, 1);
    // kv = ckv @ Wukv -> hi/lo
    gemm_mma<<<dim3(NKV_ / 128, ROWS / 128), blk, GEMM_SMEM>>>(
        ckvh, ckvl, wuh, wul, nullptr, kvh, kvl, ROWS, NKV_, LAT_, 1);

    // RoPE in hi/lo domain (q rope blocks + kr)
    rope_hl<<<(ROWS * 17 * 32 + 255) / 256, blk>>>(qkrh, qkrl);

    // attention
    cudaFuncSetAttribute(attn_mma, cudaFuncAttributeMaxDynamicSharedMemorySize, ATT_SMEM);
    attn_mma<<<dim3(SS / 128, HH, BB), blk, ATT_SMEM>>>(qkrh, qkrl, kvh, kvl, atth, attl);

    // out = att @ Wo  -> fp32
    gemm_mma<<<dim3(DIM_ / 128, ROWS / 128), blk, GEMM_SMEM>>>(
        atth, attl, woh, wol, out, nullptr, nullptr, ROWS, DIM_, NO_, 0);
}

// round 6
// speedup vs baseline: 3.3927x; 1.0029x over previous
#include <cuda_runtime.h>
#include <cuda_bf16.h>
#include <math.h>
#include <stdint.h>

// ---------------- problem constants ----------------
#define BB   2
#define SS   2048
#define DIM_ 2048
#define HH   16
#define DH_  128
#define LAT_ 512
#define DR_  64
#define NQ_  (HH * (DH_ + DR_))   // 3072
#define CS_  3712                 // combined q||kr||pad||ckv stride (29 tiles)
#define NKV_ (HH * 2 * DH_)       // 4096
#define NO_  (HH * DH_)           // 2048
#define ROWS (BB * SS)            // 4096

// ---------------- scratch (device globals; no allocation allowed) ----------
__device__ __align__(16) __nv_bfloat16 g_xh   [ROWS * (size_t)DIM_];
__device__ __align__(16) __nv_bfloat16 g_xl   [ROWS * (size_t)DIM_];
__device__ __align__(16) __nv_bfloat16 g_ph   [ROWS * (size_t)CS_];   // q|kr|pad|ckv hi
__device__ __align__(16) __nv_bfloat16 g_pl   [ROWS * (size_t)CS_];   // lo
__device__ __align__(16) __nv_bfloat16 g_kvh  [ROWS * (size_t)NKV_];
__device__ __align__(16) __nv_bfloat16 g_kvl  [ROWS * (size_t)NKV_];
__device__ __align__(16) __nv_bfloat16 g_atth [ROWS * (size_t)NO_];
__device__ __align__(16) __nv_bfloat16 g_attl [ROWS * (size_t)NO_];
// combined weight [Wq*scale | Wkr | 0 | Wdkv] transposed: CS_ x DIM_
__device__ __align__(16) __nv_bfloat16 g_wch  [CS_  * (size_t)DIM_];
__device__ __align__(16) __nv_bfloat16 g_wcl  [CS_  * (size_t)DIM_];
__device__ __align__(16) __nv_bfloat16 g_wuh  [NKV_ * (size_t)LAT_];
__device__ __align__(16) __nv_bfloat16 g_wul  [NKV_ * (size_t)LAT_];
__device__ __align__(16) __nv_bfloat16 g_woh  [DIM_ * (size_t)NO_];
__device__ __align__(16) __nv_bfloat16 g_wol  [DIM_ * (size_t)NO_];

// ---------------- PTX helpers (arch-portable) ----------
__device__ __forceinline__ uint32_t smem_u32(const void* p) {
    uint32_t a;
    asm("{ .reg .u64 t; cvta.to.shared.u64 t, %1; cvt.u32.u64 %0, t; }"
        : "=r"(a) : "l"(p));
    return a;
}
__device__ __forceinline__ void cpa16(uint32_t dst, const void* src) {
    asm volatile("cp.async.cg.shared.global [%0], [%1], 16;"
                 :: "r"(dst), "l"(src) : "memory");
}
__device__ __forceinline__ void cpa_commit() {
    asm volatile("cp.async.commit_group;" ::: "memory");
}
__device__ __forceinline__ void cpa_wait0() {
    asm volatile("cp.async.wait_group 0;" ::: "memory");
}
__device__ __forceinline__ void cpa_wait2() {
    asm volatile("cp.async.wait_group 2;" ::: "memory");
}
__device__ __forceinline__ void ldmx4(uint32_t* r, uint32_t addr) {
    asm volatile("ldmatrix.sync.aligned.m8n8.x4.shared.b16 {%0,%1,%2,%3}, [%4];"
        : "=r"(r[0]), "=r"(r[1]), "=r"(r[2]), "=r"(r[3]) : "r"(addr));
}
__device__ __forceinline__ void ldmx4t(uint32_t* r, uint32_t addr) {
    asm volatile("ldmatrix.sync.aligned.m8n8.x4.trans.shared.b16 {%0,%1,%2,%3}, [%4];"
        : "=r"(r[0]), "=r"(r[1]), "=r"(r[2]), "=r"(r[3]) : "r"(addr));
}
__device__ __forceinline__ void mma16816(float* d, const uint32_t* a, const uint32_t* b) {
    asm volatile(
        "mma.sync.aligned.m16n8k16.row.col.f32.bf16.bf16.f32 "
        "{%0,%1,%2,%3}, {%4,%5,%6,%7}, {%8,%9}, {%0,%1,%2,%3};"
        : "+f"(d[0]), "+f"(d[1]), "+f"(d[2]), "+f"(d[3])
        : "r"(a[0]), "r"(a[1]), "r"(a[2]), "r"(a[3]), "r"(b[0]), "r"(b[1]));
}

// ---------------- elementwise split (x only) ----------------
__global__ __launch_bounds__(256) void split_k(
    const float* __restrict__ A, __nv_bfloat16* __restrict__ h,
    __nv_bfloat16* __restrict__ l, int n4)
{
    int i = blockIdx.x * 256 + threadIdx.x;
    if (i >= n4) return;
    float4 v = *(const float4*)(A + (size_t)i * 4);
    __nv_bfloat16 hx = __float2bfloat16(v.x), hy = __float2bfloat16(v.y);
    __nv_bfloat16 hz = __float2bfloat16(v.z), hw = __float2bfloat16(v.w);
    __nv_bfloat162* hp = (__nv_bfloat162*)(h + (size_t)i * 4);
    hp[0] = __nv_bfloat162(hx, hy);
    hp[1] = __nv_bfloat162(hz, hw);
    __nv_bfloat162* lp = (__nv_bfloat162*)(l + (size_t)i * 4);
    lp[0] = __nv_bfloat162(__float2bfloat16(v.x - __bfloat162float(hx)),
                           __float2bfloat16(v.y - __bfloat162float(hy)));
    lp[1] = __nv_bfloat162(__float2bfloat16(v.z - __bfloat162float(hz)),
                           __float2bfloat16(v.w - __bfloat162float(hw)));
}

// ---------------- transpose + split weights: T[n][k] = alpha*B[k][n] -------
__global__ __launch_bounds__(256) void tsplitw_k(
    const float* __restrict__ B, __nv_bfloat16* __restrict__ Th,
    __nv_bfloat16* __restrict__ Tl, int K, int N, float alpha)
{
    __shared__ float tile[32][33];
    const int tx = threadIdx.x & 31, ty = threadIdx.x >> 5;
    const int n0 = blockIdx.x * 32, k0 = blockIdx.y * 32;
#pragma unroll
    for (int i = 0; i < 32; i += 8)
        tile[ty + i][tx] = B[(size_t)(k0 + ty + i) * N + n0 + tx];
    __syncthreads();
#pragma unroll
    for (int i = 0; i < 32; i += 8) {
        float v = alpha * tile[tx][ty + i];
        __nv_bfloat16 h = __float2bfloat16(v);
        size_t o = (size_t)(n0 + ty + i) * K + k0 + tx;
        Th[o] = h;
        Tl[o] = __float2bfloat16(v - __bfloat162float(h));
    }
}

// zero-pad kernel (pad rows of combined weight)
__global__ void zpad_k(__nv_bfloat16* __restrict__ h, __nv_bfloat16* __restrict__ l, int n)
{
    int i = blockIdx.x * 256 + threadIdx.x;
    if (i < n) { h[i] = __float2bfloat16(0.f); l[i] = __float2bfloat16(0.f); }
}

// ---------------- bf16 split-2 HMMA GEMM, 3-stage, fused hi/lo epilogue ----
// A: [M,K] bf16 hi/lo with row stride lda; B: [N,K] hi/lo (stride K).
#define STG_A 8192
#define STG   32768
#define GEMM_SMEM (3 * STG)

__global__ __launch_bounds__(256) void gemm_mma(
    const __nv_bfloat16* __restrict__ Ah, const __nv_bfloat16* __restrict__ Al,
    const __nv_bfloat16* __restrict__ Bh, const __nv_bfloat16* __restrict__ Bl,
    float* __restrict__ C, __nv_bfloat16* __restrict__ Ch,
    __nv_bfloat16* __restrict__ Cl, int M, int N, int K, int lda, int out_hl)
{
    extern __shared__ char smc[];
    const uint32_t sb = smem_u32(smc);
    const int t = threadIdx.x, wid = t >> 5, lane = t & 31;
    const int m0 = blockIdx.y * 128, n0 = blockIdx.x * 128;
    const int wr = (wid & 3) * 32, wc = (wid >> 2) * 64;

    float acc[2][8][4];
#pragma unroll
    for (int a = 0; a < 2; a++)
#pragma unroll
        for (int b = 0; b < 8; b++)
#pragma unroll
            for (int c = 0; c < 4; c++) acc[a][b][c] = 0.f;

    const int nk = K >> 5;

    auto load_stage = [&](int kc, int s) {
        const uint32_t base = sb + s * STG;
#pragma unroll
        for (int i = 0; i < 2; i++) {
            const int idx = t + i * 256;
            const int r = idx >> 2, c = idx & 3;
            const uint32_t sw = (uint32_t)(r * 64 + ((c ^ ((r >> 1) & 3)) * 16));
            const size_t ga = (size_t)(m0 + r) * lda + kc * 32 + c * 8;
            const size_t gb = (size_t)(n0 + r) * K + kc * 32 + c * 8;
            cpa16(base + sw,             Ah + ga);
            cpa16(base + STG_A + sw,     Al + ga);
            cpa16(base + 2 * STG_A + sw, Bh + gb);
            cpa16(base + 3 * STG_A + sw, Bl + gb);
        }
        cpa_commit();
    };

    load_stage(0, 0);
    load_stage(1, 1);
    load_stage(2, 2);

    int s = 0;
    for (int kc = 0; kc < nk; kc++) {
        cpa_wait2();
        __syncthreads();
        const uint32_t base = sb + s * STG;

#pragma unroll
        for (int ks = 0; ks < 2; ks++) {
            uint32_t ah[2][4], al[2][4];
#pragma unroll
            for (int mi = 0; mi < 2; mi++) {
                const int r = wr + mi * 16 + (lane & 15);
                const int ch = ks * 2 + (lane >> 4);
                const uint32_t ad = base + r * 64 + ((ch ^ ((r >> 1) & 3)) * 16);
                ldmx4(ah[mi], ad);
                ldmx4(al[mi], ad + STG_A);
            }
#pragma unroll
            for (int p = 0; p < 4; p++) {
                const int r = wc + p * 16 + (lane & 7) + ((lane >> 4) << 3);
                const int ch = ks * 2 + ((lane >> 3) & 1);
                const uint32_t bd = base + 2 * STG_A + r * 64 + ((ch ^ ((r >> 1) & 3)) * 16);
                uint32_t bh[4], bl[4];
                ldmx4(bh, bd);
                ldmx4(bl, bd + STG_A);
#pragma unroll
                for (int hh = 0; hh < 2; hh++) {
#pragma unroll
                    for (int mi = 0; mi < 2; mi++) {
                        float* d = acc[mi][p * 2 + hh];
                        mma16816(d, ah[mi], bh + hh * 2);
                        mma16816(d, ah[mi], bl + hh * 2);
                        mma16816(d, al[mi], bh + hh * 2);
                    }
                }
            }
        }
        __syncthreads();
        if (kc + 3 < nk) load_stage(kc + 3, s);
        else cpa_commit();
        s = (s == 2) ? 0 : s + 1;
    }

    // epilogue (C row stride == N)
#pragma unroll
    for (int mi = 0; mi < 2; mi++) {
#pragma unroll
        for (int ni = 0; ni < 8; ni++) {
            const int r0 = m0 + wr + mi * 16 + (lane >> 2);
            const int c0 = n0 + wc + ni * 8 + (lane & 3) * 2;
            if (out_hl) {
#pragma unroll
                for (int half = 0; half < 2; half++) {
                    const size_t o = (size_t)(r0 + half * 8) * N + c0;
                    const float v0 = acc[mi][ni][half * 2 + 0];
                    const float v1 = acc[mi][ni][half * 2 + 1];
                    __nv_bfloat162 hv = __floats2bfloat162_rn(v0, v1);
                    *(__nv_bfloat162*)(Ch + o) = hv;
                    *(__nv_bfloat162*)(Cl + o) = __floats2bfloat162_rn(
                        v0 - __bfloat162float(hv.x), v1 - __bfloat162float(hv.y));
                }
            } else {
                float2 v0, v1;
                v0.x = acc[mi][ni][0]; v0.y = acc[mi][ni][1];
                v1.x = acc[mi][ni][2]; v1.y = acc[mi][ni][3];
                *(float2*)&C[(size_t)r0 * N + c0]       = v0;
                *(float2*)&C[(size_t)(r0 + 8) * N + c0] = v1;
            }
        }
    }
}

// ---------------- RoPE in hi/lo domain (q rope blocks + kr block) ---------
__global__ void rope_hl(__nv_bfloat16* __restrict__ h, __nv_bfloat16* __restrict__ l)
{
    int idx = blockIdx.x * blockDim.x + threadIdx.x;   // ROWS*17*32
    if (idx >= ROWS * 17 * 32) return;
    int i   = idx & 31;
    int u   = (idx >> 5) % 17;
    int row = (idx >> 5) / 17;
    int pos = row & (SS - 1);
    float inv = powf(10000.0f, -(float)i / 32.0f);
    float ang = (float)pos * inv;
    float s, c; sincosf(ang, &s, &c);
    size_t base = (size_t)row * CS_ + (u < 16 ? u * 192 + 128 : 3072);
    float x1 = __bfloat162float(h[base + i])      + __bfloat162float(l[base + i]);
    float x2 = __bfloat162float(h[base + i + 32]) + __bfloat162float(l[base + i + 32]);
    float r1 = x1 * c - x2 * s;
    float r2 = x2 * c + x1 * s;
    __nv_bfloat16 h1 = __float2bfloat16(r1), h2 = __float2bfloat16(r2);
    h[base + i]      = h1;
    l[base + i]      = __float2bfloat16(r1 - __bfloat162float(h1));
    h[base + i + 32] = h2;
    l[base + i + 32] = __float2bfloat16(r2 - __bfloat162float(h2));
}

// ---------------- flash attention, split-2 bf16 HMMA, overlapped loads ----
#define ASTR_ 384
#define VSTR_ 256
#define OQH 0
#define OQL 49152
#define OKH 98304
#define OKL 122880
#define OVH 147456
#define OVL 163840
#define ATT_SMEM 180224

__global__ __launch_bounds__(256, 1) void attn_mma(
    const __nv_bfloat16* __restrict__ qh,  const __nv_bfloat16* __restrict__ ql,
    const __nv_bfloat16* __restrict__ kvh, const __nv_bfloat16* __restrict__ kvl,
    __nv_bfloat16* __restrict__ atth, __nv_bfloat16* __restrict__ attl)
{
    extern __shared__ char smc[];
    const uint32_t sb = smem_u32(smc);
    const int t = threadIdx.x, w = t >> 5, lane = t & 31;
    const int qt = gridDim.x - 1 - blockIdx.x;   // heavy tiles first
    const int h = blockIdx.y, b = blockIdx.z;
    const int q0 = qt * 128;
    const int rowg0 = b * SS + q0;
    const int g = lane >> 2, tq = lane & 3;
    const int qr0 = q0 + w * 16 + g;

    auto loadK = [&](int kt) {
        const int k0 = kt * 64;
#pragma unroll
        for (int it = 0; it < 6; it++) {
            const int idx = t + it * 256;        // 64*24
            const int r = idx / 24, c = idx % 24;
            const uint32_t dst = sb + r * ASTR_ + ((c ^ (r & 7)) * 16);
            const size_t rg = (size_t)(b * SS + k0 + r);
            if (c < 16) {
                const size_t go = rg * NKV_ + h * 256 + c * 8;
                cpa16(dst + OKH, kvh + go);
                cpa16(dst + OKL, kvl + go);
            } else {
                const size_t go = rg * CS_ + 3072 + (c - 16) * 8;
                cpa16(dst + OKH, qh + go);
                cpa16(dst + OKL, ql + go);
            }
        }
        cpa_commit();
    };
    auto loadV = [&](int kt) {
        const int k0 = kt * 64;
#pragma unroll
        for (int it = 0; it < 4; it++) {
            const int idx = t + it * 256;        // 64*16
            const int r = idx >> 4, c = idx & 15;
            const uint32_t dst = sb + r * VSTR_ + ((c ^ (r & 7)) * 16);
            const size_t go = (size_t)(b * SS + k0 + r) * NKV_ + h * 256 + 128 + c * 8;
            cpa16(dst + OVH, kvh + go);
            cpa16(dst + OVL, kvl + go);
        }
        cpa_commit();
    };

    // ---- prologue: Q tile + K(0) ----
#pragma unroll
    for (int it = 0; it < 12; it++) {
        const int idx = t + it * 256;            // 128*24
        const int r = idx / 24, c = idx % 24;
        const uint32_t dst = sb + r * ASTR_ + ((c ^ (r & 7)) * 16);
        const size_t go = (size_t)(rowg0 + r) * CS_ + h * 192 + c * 8;
        cpa16(dst + OQH, qh + go);
        cpa16(dst + OQL, ql + go);
    }
    cpa_commit();
    loadK(0);

    float m0 = -1e30f, m1 = -1e30f, l0 = 0.f, l1 = 0.f;
    float oacc[16][4];
#pragma unroll
    for (int i = 0; i < 16; i++)
#pragma unroll
        for (int j = 0; j < 4; j++) oacc[i][j] = 0.f;

    const int nkt = 2 * qt + 2;
    const int wkmax = q0 + w * 16 + 15;

    for (int kt = 0; kt < nkt; kt++) {
        const int k0 = kt * 64;
        cpa_wait0();          // K(kt) (and Q on first iter) resident
        __syncthreads();      // prior PV done -> V buffer free
        loadV(kt);            // V(kt) overlaps QK compute

        const bool active = (k0 <= wkmax);
        float sacc[8][4];
        if (active) {
#pragma unroll
            for (int p = 0; p < 8; p++)
#pragma unroll
                for (int c = 0; c < 4; c++) sacc[p][c] = 0.f;

            for (int kc = 0; kc < 12; kc++) {
                const int ra = w * 16 + (lane & 15);
                const int ca = kc * 2 + (lane >> 4);
                const uint32_t qa = sb + ra * ASTR_ + ((ca ^ (ra & 7)) * 16);
                uint32_t aQh[4], aQl[4];
                ldmx4(aQh, qa + OQH);
                ldmx4(aQl, qa + OQL);
#pragma unroll
                for (int g16 = 0; g16 < 4; g16++) {
                    const int rb = g16 * 16 + (lane & 7) + ((lane >> 4) << 3);
                    const int cb = kc * 2 + ((lane >> 3) & 1);
                    const uint32_t ka = sb + rb * ASTR_ + ((cb ^ (rb & 7)) * 16);
                    uint32_t bKh[4], bKl[4];
                    ldmx4(bKh, ka + OKH);
                    ldmx4(bKl, ka + OKL);
#pragma unroll
                    for (int hh = 0; hh < 2; hh++) {
                        float* d = sacc[g16 * 2 + hh];
                        mma16816(d, aQh, bKh + hh * 2);
                        mma16816(d, aQh, bKl + hh * 2);
                        mma16816(d, aQl, bKh + hh * 2);
                    }
                }
            }
        }

        cpa_wait0();          // V(kt) resident
        __syncthreads();      // all warps done with K(kt)
        if (kt + 1 < nkt) loadK(kt + 1);   // overlaps softmax + PV

        if (active) {
            if (k0 + 63 > q0 + w * 16) {
#pragma unroll
                for (int p = 0; p < 8; p++) {
                    const int colb = k0 + p * 8 + 2 * tq;
#pragma unroll
                    for (int c = 0; c < 4; c++) {
                        const int col = colb + (c & 1);
                        const int row = qr0 + ((c >> 1) << 3);
                        if (col > row) sacc[p][c] = -1e30f;
                    }
                }
            }

            float t0 = -1e30f, t1 = -1e30f;
#pragma unroll
            for (int p = 0; p < 8; p++) {
                t0 = fmaxf(t0, fmaxf(sacc[p][0], sacc[p][1]));
                t1 = fmaxf(t1, fmaxf(sacc[p][2], sacc[p][3]));
            }
            t0 = fmaxf(t0, __shfl_xor_sync(0xffffffffu, t0, 1));
            t0 = fmaxf(t0, __shfl_xor_sync(0xffffffffu, t0, 2));
            t1 = fmaxf(t1, __shfl_xor_sync(0xffffffffu, t1, 1));
            t1 = fmaxf(t1, __shfl_xor_sync(0xffffffffu, t1, 2));
            const float mn0 = fmaxf(m0, t0), mn1 = fmaxf(m1, t1);
            const float a0 = __expf(m0 - mn0), a1 = __expf(m1 - mn1);
            m0 = mn0; m1 = mn1;
            float s0 = 0.f, s1 = 0.f;
#pragma unroll
            for (int p = 0; p < 8; p++) {
                sacc[p][0] = __expf(sacc[p][0] - m0); s0 += sacc[p][0];
                sacc[p][1] = __expf(sacc[p][1] - m0); s0 += sacc[p][1];
                sacc[p][2] = __expf(sacc[p][2] - m1); s1 += sacc[p][2];
                sacc[p][3] = __expf(sacc[p][3] - m1); s1 += sacc[p][3];
            }
            s0 += __shfl_xor_sync(0xffffffffu, s0, 1);
            s0 += __shfl_xor_sync(0xffffffffu, s0, 2);
            s1 += __shfl_xor_sync(0xffffffffu, s1, 1);
            s1 += __shfl_xor_sync(0xffffffffu, s1, 2);
            l0 = l0 * a0 + s0;
            l1 = l1 * a1 + s1;

#pragma unroll
            for (int nt = 0; nt < 16; nt++) {
                oacc[nt][0] *= a0; oacc[nt][1] *= a0;
                oacc[nt][2] *= a1; oacc[nt][3] *= a1;
            }

#pragma unroll
            for (int kc2 = 0; kc2 < 4; kc2++) {
                uint32_t aPh[4], aPl[4];
#pragma unroll
                for (int u = 0; u < 4; u++) {
                    const float* pp = &sacc[kc2 * 2 + (u >> 1)][(u & 1) * 2];
                    const float p0 = pp[0], p1 = pp[1];
                    __nv_bfloat162 hv = __floats2bfloat162_rn(p0, p1);
                    aPh[u] = *(uint32_t*)&hv;
                    __nv_bfloat162 lv = __floats2bfloat162_rn(
                        p0 - __bfloat162float(hv.x), p1 - __bfloat162float(hv.y));
                    aPl[u] = *(uint32_t*)&lv;
                }
#pragma unroll
                for (int v16 = 0; v16 < 8; v16++) {
                    const int rv = kc2 * 16 + (lane & 7) + (((lane >> 3) & 1) << 3);
                    const int cv = v16 * 2 + (lane >> 4);
                    const uint32_t va = sb + rv * VSTR_ + ((cv ^ (rv & 7)) * 16);
                    uint32_t bVh[4], bVl[4];
                    ldmx4t(bVh, va + OVH);
                    ldmx4t(bVl, va + OVL);
#pragma unroll
                    for (int hh = 0; hh < 2; hh++) {
                        float* d = oacc[v16 * 2 + hh];
                        mma16816(d, aPh, bVh + hh * 2);
                        mma16816(d, aPh, bVl + hh * 2);
                        mma16816(d, aPl, bVh + hh * 2);
                    }
                }
            }
        }
    }

    // ---- epilogue ----
    const float i0 = 1.0f / l0, i1 = 1.0f / l1;
#pragma unroll
    for (int nt = 0; nt < 16; nt++) {
        const size_t base0 = (size_t)(rowg0 + w * 16 + g) * NO_ + h * 128 + nt * 8 + 2 * tq;
        const size_t base1 = base0 + (size_t)8 * NO_;
        float o0 = oacc[nt][0] * i0, o1 = oacc[nt][1] * i0;
        __nv_bfloat162 hv = __floats2bfloat162_rn(o0, o1);
        *(__nv_bfloat162*)(atth + base0) = hv;
        *(__nv_bfloat162*)(attl + base0) = __floats2bfloat162_rn(
            o0 - __bfloat162float(hv.x), o1 - __bfloat162float(hv.y));
        float o2 = oacc[nt][2] * i1, o3 = oacc[nt][3] * i1;
        __nv_bfloat162 hv2 = __floats2bfloat162_rn(o2, o3);
        *(__nv_bfloat162*)(atth + base1) = hv2;
        *(__nv_bfloat162*)(attl + base1) = __floats2bfloat162_rn(
            o2 - __bfloat162float(hv2.x), o3 - __bfloat162float(hv2.y));
    }
}

// ---------------- launch ----------------
extern "C" void kernel_launch(void* const* d_in, const int* in_sizes, int n_in,
                              void* d_out, int out_size)
{
    const float* x    = (const float*)d_in[0];
    const float* Wq   = (const float*)d_in[1];
    const float* Wdkv = (const float*)d_in[2];
    const float* Wkr  = (const float*)d_in[3];
    const float* Wukv = (const float*)d_in[4];
    const float* Wo   = (const float*)d_in[5];
    float* out = (float*)d_out;

    __nv_bfloat16 *xh, *xl, *ph, *pl, *kvh, *kvl, *atth, *attl;
    __nv_bfloat16 *wch, *wcl, *wuh, *wul, *woh, *wol;
    cudaGetSymbolAddress((void**)&xh,   g_xh);
    cudaGetSymbolAddress((void**)&xl,   g_xl);
    cudaGetSymbolAddress((void**)&ph,   g_ph);
    cudaGetSymbolAddress((void**)&pl,   g_pl);
    cudaGetSymbolAddress((void**)&kvh,  g_kvh);
    cudaGetSymbolAddress((void**)&kvl,  g_kvl);
    cudaGetSymbolAddress((void**)&atth, g_atth);
    cudaGetSymbolAddress((void**)&attl, g_attl);
    cudaGetSymbolAddress((void**)&wch,  g_wch);
    cudaGetSymbolAddress((void**)&wcl,  g_wcl);
    cudaGetSymbolAddress((void**)&wuh,  g_wuh);
    cudaGetSymbolAddress((void**)&wul,  g_wul);
    cudaGetSymbolAddress((void**)&woh,  g_woh);
    cudaGetSymbolAddress((void**)&wol,  g_wol);

    const float scale = 1.0f / sqrtf((float)(DH_ + DR_));
    dim3 blk(256);

    // launches 0-4: splits (combined weight = [Wq*scale | Wkr | 0 | Wdkv])
    split_k<<<ROWS * DIM_ / 4 / 256, blk>>>(x, xh, xl, ROWS * DIM_ / 4);           // 0
    tsplitw_k<<<dim3(NQ_ / 32, DIM_ / 32), blk>>>(Wq, wch, wcl, DIM_, NQ_, scale); // 1
    tsplitw_k<<<dim3(DR_ / 32, DIM_ / 32), blk>>>(Wkr,
        wch + (size_t)NQ_ * DIM_, wcl + (size_t)NQ_ * DIM_, DIM_, DR_, 1.0f);      // 2
    zpad_k<<<(64 * DIM_ + 255) / 256, blk>>>(
        wch + (size_t)(NQ_ + DR_) * DIM_, wcl + (size_t)(NQ_ + DR_) * DIM_, 64 * DIM_); // 3
    tsplitw_k<<<dim3(LAT_ / 32, DIM_ / 32), blk>>>(Wdkv,
        wch + (size_t)(NQ_ + DR_ + 64) * DIM_, wcl + (size_t)(NQ_ + DR_ + 64) * DIM_,
        DIM_, LAT_, 1.0f);                                                         // 4

    cudaFuncSetAttribute(gemm_mma, cudaFuncAttributeMaxDynamicSharedMemorySize, GEMM_SMEM);

    // launch 5 (ncu capture target): [q | kr | pad | ckv] = x @ Wc -> hi/lo
    gemm_mma<<<dim3(CS_ / 128, ROWS / 128), blk, GEMM_SMEM>>>(
        xh, xl, wch, wcl, nullptr, ph, pl, ROWS, CS_, DIM_, DIM_, 1);

    // remaining weight splits
    tsplitw_k<<<dim3(NKV_ / 32, LAT_ / 32), blk>>>(Wukv, wuh, wul, LAT_, NKV_, 1.0f);
    tsplitw_k<<<dim3(DIM_ / 32, NO_  / 32), blk>>>(Wo,   woh, wol, NO_,  DIM_, 1.0f);

    // kv = ckv @ Wukv  (ckv read in place from combined buffer, lda=CS_)
    gemm_mma<<<dim3(NKV_ / 128, ROWS / 128), blk, GEMM_SMEM>>>(
        ph + 3200, pl + 3200, wuh, wul, nullptr, kvh, kvl, ROWS, NKV_, LAT_, CS_, 1);

    // RoPE in hi/lo domain
    rope_hl<<<(ROWS * 17 * 32 + 255) / 256, blk>>>(ph, pl);

    // attention
    cudaFuncSetAttribute(attn_mma, cudaFuncAttributeMaxDynamicSharedMemorySize, ATT_SMEM);
    attn_mma<<<dim3(SS / 128, HH, BB), blk, ATT_SMEM>>>(ph, pl, kvh, kvl, atth, attl);

    // out = att @ Wo  -> fp32
    gemm_mma<<<dim3(DIM_ / 128, ROWS / 128), blk, GEMM_SMEM>>>(
        atth, attl, woh, wol, out, nullptr, nullptr, ROWS, DIM_, NO_, NO_, 0);
}